// round 6
// baseline (speedup 1.0000x reference)
#include <cuda_runtime.h>
#include <cstdint>

#define DIM_NODE 64
#define DIM_EDGE 32
#define D_IN1    160
#define OUT_DIM  64
#define MAX_NODES 50000
#define E_TILE   128
#define NEG_SLOPE 0.01f

// Per-node precomputed partials: P[n][0:128] = x[n]@W1a^T, P[n][128:256] = x[n]@W1b^T
__device__ float g_P[(size_t)MAX_NODES * 256];

__device__ __forceinline__ float to_tf32(float x) {
    uint32_t u; asm("cvt.rna.tf32.f32 %0, %1;" : "=r"(u) : "f"(x));
    return __uint_as_float(u);
}
__device__ __forceinline__ void mma_tf32(float* d, const uint32_t* a, const uint32_t* b) {
    asm volatile(
        "mma.sync.aligned.m16n8k8.row.col.f32.tf32.tf32.f32 "
        "{%0,%1,%2,%3}, {%4,%5,%6,%7}, {%8,%9}, {%0,%1,%2,%3};"
        : "+f"(d[0]), "+f"(d[1]), "+f"(d[2]), "+f"(d[3])
        : "r"(a[0]), "r"(a[1]), "r"(a[2]), "r"(a[3]), "r"(b[0]), "r"(b[1]));
}
__device__ __forceinline__ void ldsm_x4(uint32_t* r, uint32_t addr) {
    asm volatile("ldmatrix.sync.aligned.m8n8.x4.shared.b16 {%0,%1,%2,%3}, [%4];"
        : "=r"(r[0]), "=r"(r[1]), "=r"(r[2]), "=r"(r[3]) : "r"(addr));
}
__device__ __forceinline__ uint32_t smem_u32(const void* p) {
    uint32_t a;
    asm("{ .reg .u64 t; cvta.to.shared.u64 t, %1; cvt.u32.u64 %0, t; }" : "=r"(a) : "l"(p));
    return a;
}

// ---------------------------------------------------------------------------
// SMEM layout (float offsets).  Region0 [128][132] overlaid:
//   staging/GEMM1: EA [128][36] @0, W1C [128][36] @4608
//   after GEMM1  : H  [128][132] @0
// W2 [64][132] @16896, b1 @25344, b2 @25472, src @25536, dst @25664
// ---------------------------------------------------------------------------
#define EA_F    0
#define W1C_F   4608
#define H_F     0
#define W2_F    16896
#define B1_F    25344
#define B2_F    25472
#define SRC_F   25536
#define DST_F   25664
#define SMEM_EDGE_FLOATS 25792          // 103168 bytes

// ---------------------------------------------------------------------------
// Kernel 1: node precompute.  64 nodes/block, 256 threads, 8x8 microtile.
// ---------------------------------------------------------------------------
__global__ __launch_bounds__(256, 2) void k_precompute(
    const float* __restrict__ x, const float* __restrict__ W1, int n_nodes)
{
    extern __shared__ float sm[];
    float* s_w = sm;               // [64][257]
    float* s_x = sm + 64 * 257;    // [64][68]
    const int t = threadIdx.x;

    #pragma unroll
    for (int i = 0; i < 64; ++i) {
        int idx = i * 256 + t;
        int c = idx >> 6, d = idx & 63;
        float v = (c < 128) ? W1[c * D_IN1 + d] : W1[(c - 128) * D_IN1 + 64 + d];
        s_w[d * 257 + c] = v;
    }
    const int node0 = blockIdx.x * 64;
    #pragma unroll
    for (int i = 0; i < 16; ++i) {
        int idx = i * 256 + t;
        int n = idx >> 6, d = idx & 63;
        int gn = node0 + n;
        s_x[n * 68 + d] = (gn < n_nodes) ? x[(size_t)gn * DIM_NODE + d] : 0.f;
    }
    __syncthreads();

    const int n0 = t & 7;
    const int c0 = (t >> 3) * 8;
    float acc[8][8];
    #pragma unroll
    for (int i = 0; i < 8; ++i)
        #pragma unroll
        for (int j = 0; j < 8; ++j) acc[i][j] = 0.f;

    #pragma unroll 4
    for (int d = 0; d < 64; ++d) {
        float xa[8], wb[8];
        #pragma unroll
        for (int i = 0; i < 8; ++i) xa[i] = s_x[(n0 + 8 * i) * 68 + d];
        #pragma unroll
        for (int j = 0; j < 8; ++j) wb[j] = s_w[d * 257 + c0 + j];
        #pragma unroll
        for (int i = 0; i < 8; ++i)
            #pragma unroll
            for (int j = 0; j < 8; ++j)
                acc[i][j] = fmaf(xa[i], wb[j], acc[i][j]);
    }
    #pragma unroll
    for (int i = 0; i < 8; ++i) {
        int gn = node0 + n0 + 8 * i;
        if (gn < n_nodes) {
            float4* p = (float4*)(g_P + (size_t)gn * 256 + c0);
            p[0] = make_float4(acc[i][0], acc[i][1], acc[i][2], acc[i][3]);
            p[1] = make_float4(acc[i][4], acc[i][5], acc[i][6], acc[i][7]);
        }
    }
}

// ---------------------------------------------------------------------------
// Kernel 2: persistent mma.sync tf32 edge MLP, ldmatrix + ea prefetch.
// ---------------------------------------------------------------------------
__global__ __launch_bounds__(256, 2) void k_edge(
    const int*   __restrict__ eidx,
    const float* __restrict__ ea,
    const float* __restrict__ W1,
    const float* __restrict__ b1,
    const float* __restrict__ W2g,
    const float* __restrict__ b2,
    float*       __restrict__ out,
    int E, int n_tiles)
{
    extern __shared__ float sm[];
    const uint32_t sb = smem_u32(sm);
    const int t   = threadIdx.x;
    const int wid = t >> 5;
    const int lid = t & 31;
    const int qr  = lid >> 2;      // 0..7
    const int ql  = lid & 3;       // 0..3
    const int wm  = wid & 3;       // warp M coord (rows of 32)
    const int wn  = wid >> 2;      // warp N coord
    const int lm  = lid & 7;       // ldmatrix row lane
    const int lq  = lid >> 3;      // ldmatrix matrix index 0..3

    int* s_src = (int*)(sm + SRC_F);
    int* s_dst = (int*)(sm + DST_F);

    // ---- ldmatrix per-lane base addresses (constant for whole kernel) ----
    uint32_t a1b[2], b1b[4], a2b[2], b2b[2];
    #pragma unroll
    for (int i = 0; i < 2; ++i)
        a1b[i] = sb + 4u * (EA_F + (wm * 32 + i * 16 + (lq & 1) * 8 + lm) * 36 + (lq >> 1) * 4);
    #pragma unroll
    for (int jj = 0; jj < 4; ++jj)
        b1b[jj] = sb + 4u * (W1C_F + (wn * 64 + jj * 16 + (lq >> 1) * 8 + lm) * 36 + (lq & 1) * 4);
    #pragma unroll
    for (int i = 0; i < 2; ++i)
        a2b[i] = sb + 4u * (H_F + (wm * 32 + i * 16 + (lq & 1) * 8 + lm) * 132 + (lq >> 1) * 4);
    #pragma unroll
    for (int jj = 0; jj < 2; ++jj)
        b2b[jj] = sb + 4u * (W2_F + (wn * 32 + jj * 16 + (lq >> 1) * 8 + lm) * 132 + (lq & 1) * 4);

    // ======== CTA prologue: persistent W2 + biases ========
    #pragma unroll
    for (int i = 0; i < 8; ++i) {
        int idx = i * 256 + t;                // 0..2047 float4s
        int n = idx >> 5, kc = idx & 31;
        float4 v = ((const float4*)W2g)[n * 32 + kc];
        v.x = to_tf32(v.x); v.y = to_tf32(v.y); v.z = to_tf32(v.z); v.w = to_tf32(v.w);
        *(float4*)(sm + W2_F + n * 132 + kc * 4) = v;
    }
    if (t < 128)      sm[B1_F + t] = b1[t];
    else if (t < 192) sm[B2_F + t - 128] = b2[t - 128];
    __syncthreads();

    float2 bb2[4];
    #pragma unroll
    for (int j = 0; j < 4; ++j)
        bb2[j] = *(const float2*)(sm + B2_F + wn * 32 + j * 8 + 2 * ql);
    const float4 bb1 = *(const float4*)(sm + B1_F + 4 * lid);

    // ---- prefetch state (next tile's ea + indices in registers) ----
    uint4 pf[4];
    int pidx = 0;
    const int tidx128 = t & 127;

#define PREFETCH(PT) do {                                                      \
    int _pt = (PT);                                                            \
    if (_pt < n_tiles) {                                                       \
        int _eb = _pt * E_TILE;                                                \
        _Pragma("unroll")                                                      \
        for (int _i = 0; _i < 4; ++_i) {                                       \
            int _idx = _i * 256 + t;                                           \
            int _m = _idx >> 3, _kc = _idx & 7;                                \
            int _ge = _eb + _m;                                                \
            pf[_i] = (_ge < E)                                                 \
                ? *(const uint4*)(ea + (size_t)_ge * DIM_EDGE + _kc * 4)       \
                : make_uint4(0u, 0u, 0u, 0u);                                  \
        }                                                                      \
        int _e2 = _eb + tidx128;                                               \
        pidx = (_e2 < E) ? ((t < 128) ? eidx[_e2] : eidx[E + _e2]) : 0;        \
    } } while (0)

    PREFETCH(blockIdx.x);

    // ======== persistent tile loop ========
    for (int tile = blockIdx.x; tile < n_tiles; tile += gridDim.x) {
        // ---- stage current tile: ea from prefetch regs, W1c from gmem ----
        #pragma unroll
        for (int i = 0; i < 4; ++i) {
            int idx = i * 256 + t;
            int m = idx >> 3, kc = idx & 7;
            float4 v = make_float4(__uint_as_float(pf[i].x), __uint_as_float(pf[i].y),
                                   __uint_as_float(pf[i].z), __uint_as_float(pf[i].w));
            v.x = to_tf32(v.x); v.y = to_tf32(v.y); v.z = to_tf32(v.z); v.w = to_tf32(v.w);
            *(float4*)(sm + EA_F + m * 36 + kc * 4) = v;
        }
        if (t < 128) s_src[tidx128] = pidx;
        else         s_dst[tidx128] = pidx;
        #pragma unroll
        for (int i = 0; i < 4; ++i) {
            int idx = i * 256 + t;
            int n = idx >> 3, kc = idx & 7;
            float4 v = *(const float4*)(W1 + n * D_IN1 + 128 + kc * 4);
            v.x = to_tf32(v.x); v.y = to_tf32(v.y); v.z = to_tf32(v.z); v.w = to_tf32(v.w);
            *(float4*)(sm + W1C_F + n * 36 + kc * 4) = v;
        }
        __syncthreads();                       // (A)

        // ---- GEMM1: C1[128x128] = ea @ W1c^T  (M=32,N=64 per warp) ----
        float acc1[2][8][4];
        #pragma unroll
        for (int i = 0; i < 2; ++i)
            #pragma unroll
            for (int j = 0; j < 8; ++j)
                #pragma unroll
                for (int c = 0; c < 4; ++c) acc1[i][j][c] = 0.f;

        #pragma unroll
        for (int kt = 0; kt < 4; ++kt) {
            uint32_t A[2][4], B[4][4];
            ldsm_x4(A[0], a1b[0] + kt * 32);
            ldsm_x4(A[1], a1b[1] + kt * 32);
            #pragma unroll
            for (int jj = 0; jj < 4; ++jj)
                ldsm_x4(B[jj], b1b[jj] + kt * 32);
            #pragma unroll
            for (int i = 0; i < 2; ++i)
                #pragma unroll
                for (int j = 0; j < 8; ++j)
                    mma_tf32(acc1[i][j], A[i], &B[j >> 1][(j & 1) * 2]);
        }
        __syncthreads();                       // (B)

        // ---- STS C1 -> s_h [128 m][132] ----
        #pragma unroll
        for (int i = 0; i < 2; ++i) {
            int r = wm * 32 + i * 16 + qr;
            #pragma unroll
            for (int j = 0; j < 8; ++j) {
                int c = wn * 64 + j * 8 + 2 * ql;
                *(float2*)(sm + H_F + r * 132 + c)       = make_float2(acc1[i][j][0], acc1[i][j][1]);
                *(float2*)(sm + H_F + (r + 8) * 132 + c) = make_float2(acc1[i][j][2], acc1[i][j][3]);
            }
        }
        __syncthreads();                       // (C)

        // ---- Phase B: h = tf32(leaky(C1 + P_src + P_dst + b1)) in place ----
        {
            const int m0 = wid * 16;
            #pragma unroll
            for (int g = 0; g < 16; g += 4) {
                float4 vs[4], vd[4], hh[4];
                #pragma unroll
                for (int r = 0; r < 4; ++r) {
                    int m = m0 + g + r;
                    vs[r] = *(const float4*)(g_P + (size_t)s_src[m] * 256 + 4 * lid);
                    vd[r] = *(const float4*)(g_P + (size_t)s_dst[m] * 256 + 128 + 4 * lid);
                }
                #pragma unroll
                for (int r = 0; r < 4; ++r)
                    hh[r] = *(const float4*)(sm + H_F + (m0 + g + r) * 132 + 4 * lid);
                #pragma unroll
                for (int r = 0; r < 4; ++r) {
                    float h0 = hh[r].x + vs[r].x + vd[r].x + bb1.x;
                    float h1 = hh[r].y + vs[r].y + vd[r].y + bb1.y;
                    float h2 = hh[r].z + vs[r].z + vd[r].z + bb1.z;
                    float h3 = hh[r].w + vs[r].w + vd[r].w + bb1.w;
                    h0 = (h0 >= 0.f) ? h0 : NEG_SLOPE * h0;
                    h1 = (h1 >= 0.f) ? h1 : NEG_SLOPE * h1;
                    h2 = (h2 >= 0.f) ? h2 : NEG_SLOPE * h2;
                    h3 = (h3 >= 0.f) ? h3 : NEG_SLOPE * h3;
                    *(float4*)(sm + H_F + (m0 + g + r) * 132 + 4 * lid) =
                        make_float4(to_tf32(h0), to_tf32(h1), to_tf32(h2), to_tf32(h3));
                }
            }
        }
        __syncthreads();                       // (D)

        // ---- prefetch next tile (LDGs hidden under GEMM2) ----
        PREFETCH(tile + gridDim.x);

        // ---- GEMM2: C2[128x64] = h @ W2^T  (M=32,N=32 per warp) ----
        float acc2[2][4][4];
        #pragma unroll
        for (int i = 0; i < 2; ++i)
            #pragma unroll
            for (int j = 0; j < 4; ++j)
                #pragma unroll
                for (int c = 0; c < 4; ++c) acc2[i][j][c] = 0.f;

        #pragma unroll
        for (int kt = 0; kt < 16; ++kt) {
            uint32_t A[2][4], B[2][4];
            ldsm_x4(A[0], a2b[0] + kt * 32);
            ldsm_x4(A[1], a2b[1] + kt * 32);
            ldsm_x4(B[0], b2b[0] + kt * 32);
            ldsm_x4(B[1], b2b[1] + kt * 32);
            #pragma unroll
            for (int i = 0; i < 2; ++i)
                #pragma unroll
                for (int j = 0; j < 4; ++j)
                    mma_tf32(acc2[i][j], A[i], &B[j >> 1][(j & 1) * 2]);
        }

        // ---- Epilogue: direct STG from C2 fragments (+b2) ----
        #pragma unroll
        for (int i = 0; i < 2; ++i) {
            int r = wm * 32 + i * 16 + qr;
            int ge0 = tile * E_TILE + r;
            int ge1 = ge0 + 8;
            #pragma unroll
            for (int j = 0; j < 4; ++j) {
                int c = wn * 32 + j * 8 + 2 * ql;
                if (ge0 < E)
                    *(float2*)(out + (size_t)ge0 * OUT_DIM + c) =
                        make_float2(acc2[i][j][0] + bb2[j].x, acc2[i][j][1] + bb2[j].y);
                if (ge1 < E)
                    *(float2*)(out + (size_t)ge1 * OUT_DIM + c) =
                        make_float2(acc2[i][j][2] + bb2[j].x, acc2[i][j][3] + bb2[j].y);
            }
        }
        __syncthreads();                       // (E) region0 free for next staging
    }
#undef PREFETCH
}

// ---------------------------------------------------------------------------
extern "C" void kernel_launch(void* const* d_in, const int* in_sizes, int n_in,
                              void* d_out, int out_size)
{
    const float* x    = (const float*)d_in[0];
    const int*   eidx = (const int*)  d_in[1];
    const float* ea   = (const float*)d_in[2];
    const float* W1   = (const float*)d_in[3];
    const float* b1   = (const float*)d_in[4];
    const float* W2   = (const float*)d_in[5];
    const float* b2   = (const float*)d_in[6];
    float* out = (float*)d_out;

    int n_nodes = in_sizes[0] / DIM_NODE;
    if (n_nodes > MAX_NODES) n_nodes = MAX_NODES;
    int E = in_sizes[2] / DIM_EDGE;
    int n_tiles = (E + E_TILE - 1) / E_TILE;

    const int smem1 = (64 * 257 + 64 * 68) * 4;       // 83200 B
    const int smem2 = SMEM_EDGE_FLOATS * 4;           // 103168 B

    cudaFuncSetAttribute(k_precompute, cudaFuncAttributeMaxDynamicSharedMemorySize, smem1);
    cudaFuncSetAttribute(k_edge,       cudaFuncAttributeMaxDynamicSharedMemorySize, smem2);

    int n_blocks = 148 * 8;
    if (n_blocks > n_tiles) n_blocks = n_tiles;

    k_precompute<<<(n_nodes + 63) / 64, 256, smem1>>>(x, W1, n_nodes);
    k_edge<<<n_blocks, 256, smem2>>>(eidx, ea, W1, b1, W2, b2, out, E, n_tiles);
}

// round 7
// speedup vs baseline: 1.2214x; 1.2214x over previous
#include <cuda_runtime.h>
#include <cuda_fp16.h>
#include <cstdint>

#define DIM_NODE 64
#define DIM_EDGE 32
#define D_IN1    160
#define OUT_DIM  64
#define MAX_NODES 50000
#define E_TILE   128
#define NEG_SLOPE 0.01f

// Per-node precomputed partials: P[n][0:128] = x[n]@W1a^T, P[n][128:256] = x[n]@W1b^T
__device__ float g_P[(size_t)MAX_NODES * 256];

__device__ __forceinline__ void mma_f16(float* d, const uint32_t* a, const uint32_t* b) {
    asm volatile(
        "mma.sync.aligned.m16n8k16.row.col.f32.f16.f16.f32 "
        "{%0,%1,%2,%3}, {%4,%5,%6,%7}, {%8,%9}, {%0,%1,%2,%3};"
        : "+f"(d[0]), "+f"(d[1]), "+f"(d[2]), "+f"(d[3])
        : "r"(a[0]), "r"(a[1]), "r"(a[2]), "r"(a[3]), "r"(b[0]), "r"(b[1]));
}
__device__ __forceinline__ void ldsm_x4(uint32_t* r, uint32_t addr) {
    asm volatile("ldmatrix.sync.aligned.m8n8.x4.shared.b16 {%0,%1,%2,%3}, [%4];"
        : "=r"(r[0]), "=r"(r[1]), "=r"(r[2]), "=r"(r[3]) : "r"(addr));
}
__device__ __forceinline__ uint32_t smem_u32(const void* p) {
    uint32_t a;
    asm("{ .reg .u64 t; cvta.to.shared.u64 t, %1; cvt.u32.u64 %0, t; }" : "=r"(a) : "l"(p));
    return a;
}
__device__ __forceinline__ uint32_t pack_h2(float a, float b) {
    __half2 h = __floats2half2_rn(a, b);
    return *(uint32_t*)&h;
}

// ---------------------------------------------------------------------------
// SMEM layout (BYTE offsets):
//   C1 region  @0      : f32 [128][132], stride 528B, 67584B total.
//       - EA fp16 [128][40h] stride 80B lives at @0 during staging/GEMM1.
//       - h fp16 written in place per warp chunk: byte 8448*(m>>4) + 272*(m&15).
//   W1C @67584 : fp16 [128][40h] stride 80B, persistent, 10240B
//   W2  @77824 : fp16 [64][136h] stride 272B, persistent, 17408B
//   b1 @95232, b2 @95744, src @96000, dst @96512  -> total 97024B
// ---------------------------------------------------------------------------
#define EA_B    0u
#define W1C_B   67584u
#define W2_B    77824u
#define B1_B    95232u
#define B2_B    95744u
#define SRC_B   96000u
#define DST_B   96512u
#define SMEM_EDGE_BYTES 97024u

// ---------------------------------------------------------------------------
// Kernel 1: node precompute.  64 nodes/block, 256 threads, 8x8 microtile. (f32 exact)
// ---------------------------------------------------------------------------
__global__ __launch_bounds__(256, 2) void k_precompute(
    const float* __restrict__ x, const float* __restrict__ W1, int n_nodes)
{
    extern __shared__ float sm[];
    float* s_w = sm;               // [64][257]
    float* s_x = sm + 64 * 257;    // [64][68]
    const int t = threadIdx.x;

    #pragma unroll
    for (int i = 0; i < 64; ++i) {
        int idx = i * 256 + t;
        int c = idx >> 6, d = idx & 63;
        float v = (c < 128) ? W1[c * D_IN1 + d] : W1[(c - 128) * D_IN1 + 64 + d];
        s_w[d * 257 + c] = v;
    }
    const int node0 = blockIdx.x * 64;
    #pragma unroll
    for (int i = 0; i < 16; ++i) {
        int idx = i * 256 + t;
        int n = idx >> 6, d = idx & 63;
        int gn = node0 + n;
        s_x[n * 68 + d] = (gn < n_nodes) ? x[(size_t)gn * DIM_NODE + d] : 0.f;
    }
    __syncthreads();

    const int n0 = t & 7;
    const int c0 = (t >> 3) * 8;
    float acc[8][8];
    #pragma unroll
    for (int i = 0; i < 8; ++i)
        #pragma unroll
        for (int j = 0; j < 8; ++j) acc[i][j] = 0.f;

    #pragma unroll 4
    for (int d = 0; d < 64; ++d) {
        float xa[8], wb[8];
        #pragma unroll
        for (int i = 0; i < 8; ++i) xa[i] = s_x[(n0 + 8 * i) * 68 + d];
        #pragma unroll
        for (int j = 0; j < 8; ++j) wb[j] = s_w[d * 257 + c0 + j];
        #pragma unroll
        for (int i = 0; i < 8; ++i)
            #pragma unroll
            for (int j = 0; j < 8; ++j)
                acc[i][j] = fmaf(xa[i], wb[j], acc[i][j]);
    }
    #pragma unroll
    for (int i = 0; i < 8; ++i) {
        int gn = node0 + n0 + 8 * i;
        if (gn < n_nodes) {
            float4* p = (float4*)(g_P + (size_t)gn * 256 + c0);
            p[0] = make_float4(acc[i][0], acc[i][1], acc[i][2], acc[i][3]);
            p[1] = make_float4(acc[i][4], acc[i][5], acc[i][6], acc[i][7]);
        }
    }
}

// ---------------------------------------------------------------------------
// Kernel 2: persistent fp16 mma edge MLP.  128 edges/tile, 8 warps/CTA.
// ---------------------------------------------------------------------------
__global__ __launch_bounds__(256, 2) void k_edge(
    const int*   __restrict__ eidx,
    const float* __restrict__ ea,
    const float* __restrict__ W1,
    const float* __restrict__ b1,
    const float* __restrict__ W2g,
    const float* __restrict__ b2,
    float*       __restrict__ out,
    int E, int n_tiles)
{
    extern __shared__ __align__(16) char smc[];
    const uint32_t sb = smem_u32(smc);
    const int t   = threadIdx.x;
    const int wid = t >> 5;
    const int lid = t & 31;
    const int qr  = lid >> 2;      // 0..7
    const int ql  = lid & 3;       // 0..3
    const int wm  = wid & 3;       // warp M coord (rows of 32)
    const int wn  = wid >> 2;      // warp N coord
    const int lm  = lid & 7;
    const int lq3 = lid >> 3;      // 0..3 (matrix id)
    const int lq4 = lid >> 4;      // 0..1

    int*   s_src = (int*)(smc + SRC_B);
    int*   s_dst = (int*)(smc + DST_B);
    float* s_b1  = (float*)(smc + B1_B);
    float* s_b2  = (float*)(smc + B2_B);

    // ======== CTA prologue: persistent W1C (fp16), W2 (fp16), biases ========
    {   // W1C: row n = t>>1, half hs = t&1 (16 cols)
        int n = t >> 1, hs = t & 1;
        const float4* src = (const float4*)(W1 + n * D_IN1 + 128 + hs * 16);
        float4 v0 = src[0], v1 = src[1], v2 = src[2], v3 = src[3];
        uint4 p0 = make_uint4(pack_h2(v0.x, v0.y), pack_h2(v0.z, v0.w),
                              pack_h2(v1.x, v1.y), pack_h2(v1.z, v1.w));
        uint4 p1 = make_uint4(pack_h2(v2.x, v2.y), pack_h2(v2.z, v2.w),
                              pack_h2(v3.x, v3.y), pack_h2(v3.z, v3.w));
        *(uint4*)(smc + W1C_B + n * 80 + hs * 32)      = p0;
        *(uint4*)(smc + W1C_B + n * 80 + hs * 32 + 16) = p1;
    }
    {   // W2: row n = t>>2, quarter q = t&3 (32 cols)
        int n = t >> 2, q = t & 3;
        const float4* src = (const float4*)(W2g + n * 128 + q * 32);
        #pragma unroll
        for (int s = 0; s < 2; ++s) {
            float4 v0 = src[4 * s + 0], v1 = src[4 * s + 1],
                   v2 = src[4 * s + 2], v3 = src[4 * s + 3];
            uint4 pa = make_uint4(pack_h2(v0.x, v0.y), pack_h2(v0.z, v0.w),
                                  pack_h2(v1.x, v1.y), pack_h2(v1.z, v1.w));
            uint4 pb = make_uint4(pack_h2(v2.x, v2.y), pack_h2(v2.z, v2.w),
                                  pack_h2(v3.x, v3.y), pack_h2(v3.z, v3.w));
            *(uint4*)(smc + W2_B + n * 272 + q * 64 + s * 32)      = pa;
            *(uint4*)(smc + W2_B + n * 272 + q * 64 + s * 32 + 16) = pb;
        }
    }
    if (t < 128)      s_b1[t] = b1[t];
    else if (t < 192) s_b2[t - 128] = b2[t - 128];
    __syncthreads();

    float2 bb2[4];
    #pragma unroll
    for (int j = 0; j < 4; ++j)
        bb2[j] = *(const float2*)(s_b2 + wn * 32 + j * 8 + 2 * ql);
    const float4 bb1 = *(const float4*)(s_b1 + 4 * lid);

    // ---- ldmatrix per-lane base addresses (constant for whole kernel) ----
    uint32_t a1b[2], b1b[4], a2b[2], b2b[2];
    #pragma unroll
    for (int i = 0; i < 2; ++i)
        a1b[i] = sb + EA_B + (uint32_t)((wm * 32 + i * 16 + ((lq3 & 1) << 3) + lm) * 80)
               + (uint32_t)((lq3 >> 1) * 16);
    #pragma unroll
    for (int jj = 0; jj < 4; ++jj)
        b1b[jj] = sb + W1C_B + (uint32_t)((wn * 64 + jj * 16 + lq4 * 8 + lm) * 80)
                + (uint32_t)((lq3 & 1) * 16);
    #pragma unroll
    for (int i = 0; i < 2; ++i)
        a2b[i] = sb + 8448u * (uint32_t)(wm * 2 + i)
               + (uint32_t)((((lq3 & 1) << 3) + lm) * 272) + (uint32_t)((lq3 >> 1) * 16);
    #pragma unroll
    for (int jj = 0; jj < 2; ++jj)
        b2b[jj] = sb + W2_B + (uint32_t)((wn * 32 + jj * 16 + lq4 * 8 + lm) * 272)
                + (uint32_t)((lq3 & 1) * 16);

    // ======== persistent tile loop ========
    for (int tile = blockIdx.x; tile < n_tiles; tile += gridDim.x) {
        const int ebase = tile * E_TILE;

        // ---- stage ea -> fp16 [128][40h] ----
        {
            int m = t >> 1, hs = t & 1;
            int ge = ebase + m;
            float4 v0, v1, v2, v3;
            if (ge < E) {
                const float4* src = (const float4*)(ea + (size_t)ge * DIM_EDGE + hs * 16);
                v0 = src[0]; v1 = src[1]; v2 = src[2]; v3 = src[3];
            } else {
                v0 = v1 = v2 = v3 = make_float4(0.f, 0.f, 0.f, 0.f);
            }
            uint4 p0 = make_uint4(pack_h2(v0.x, v0.y), pack_h2(v0.z, v0.w),
                                  pack_h2(v1.x, v1.y), pack_h2(v1.z, v1.w));
            uint4 p1 = make_uint4(pack_h2(v2.x, v2.y), pack_h2(v2.z, v2.w),
                                  pack_h2(v3.x, v3.y), pack_h2(v3.z, v3.w));
            *(uint4*)(smc + EA_B + m * 80 + hs * 32)      = p0;
            *(uint4*)(smc + EA_B + m * 80 + hs * 32 + 16) = p1;
        }
        if (t < 128) {
            int e = ebase + t;
            s_src[t] = (e < E) ? eidx[e] : 0;
        } else {
            int e = ebase + (t - 128);
            s_dst[t - 128] = (e < E) ? eidx[E + e] : 0;
        }
        __syncthreads();                       // (A)

        // ---- GEMM1: C1[128x128] = ea @ W1c^T  (fp16, K=32: 2 ksteps) ----
        float acc1[2][8][4];
        #pragma unroll
        for (int i = 0; i < 2; ++i)
            #pragma unroll
            for (int j = 0; j < 8; ++j)
                #pragma unroll
                for (int c = 0; c < 4; ++c) acc1[i][j][c] = 0.f;

        #pragma unroll
        for (int ks = 0; ks < 2; ++ks) {
            uint32_t A[2][4], B[4][4];
            ldsm_x4(A[0], a1b[0] + ks * 32);
            ldsm_x4(A[1], a1b[1] + ks * 32);
            #pragma unroll
            for (int jj = 0; jj < 4; ++jj)
                ldsm_x4(B[jj], b1b[jj] + ks * 32);
            #pragma unroll
            for (int i = 0; i < 2; ++i)
                #pragma unroll
                for (int j = 0; j < 8; ++j)
                    mma_f16(acc1[i][j], A[i], &B[j >> 1][(j & 1) * 2]);
        }
        __syncthreads();                       // (B) all EA reads done

        // ---- STS C1 (f32) -> region0 [128][132] ----
        #pragma unroll
        for (int i = 0; i < 2; ++i) {
            int r = wm * 32 + i * 16 + qr;
            #pragma unroll
            for (int j = 0; j < 8; ++j) {
                int c = wn * 64 + j * 8 + 2 * ql;
                *(float2*)(smc + (size_t)(r * 132 + c) * 4)       = make_float2(acc1[i][j][0], acc1[i][j][1]);
                *(float2*)(smc + (size_t)((r + 8) * 132 + c) * 4) = make_float2(acc1[i][j][2], acc1[i][j][3]);
            }
        }
        __syncthreads();                       // (C)

        // ---- Phase B: h = fp16(leaky(C1 + P_src + P_dst + b1)), in place ----
        {
            const int m0 = wid * 16;
            const uint32_t hbase = 8448u * (uint32_t)wid;
            #pragma unroll
            for (int g = 0; g < 16; g += 4) {
                float4 vs[4], vd[4], hh[4];
                #pragma unroll
                for (int r = 0; r < 4; ++r) {
                    int m = m0 + g + r;
                    vs[r] = *(const float4*)(g_P + (size_t)s_src[m] * 256 + 4 * lid);
                    vd[r] = *(const float4*)(g_P + (size_t)s_dst[m] * 256 + 128 + 4 * lid);
                }
                #pragma unroll
                for (int r = 0; r < 4; ++r)
                    hh[r] = *(const float4*)(smc + (size_t)(m0 + g + r) * 528 + 16 * lid);
                #pragma unroll
                for (int r = 0; r < 4; ++r) {
                    float h0 = hh[r].x + vs[r].x + vd[r].x + bb1.x;
                    float h1 = hh[r].y + vs[r].y + vd[r].y + bb1.y;
                    float h2 = hh[r].z + vs[r].z + vd[r].z + bb1.z;
                    float h3 = hh[r].w + vs[r].w + vd[r].w + bb1.w;
                    h0 = (h0 >= 0.f) ? h0 : NEG_SLOPE * h0;
                    h1 = (h1 >= 0.f) ? h1 : NEG_SLOPE * h1;
                    h2 = (h2 >= 0.f) ? h2 : NEG_SLOPE * h2;
                    h3 = (h3 >= 0.f) ? h3 : NEG_SLOPE * h3;
                    *(uint2*)(smc + hbase + 272u * (uint32_t)(g + r) + 8 * lid) =
                        make_uint2(pack_h2(h0, h1), pack_h2(h2, h3));
                }
            }
        }
        __syncthreads();                       // (D)

        // ---- GEMM2: C2[128x64] = h @ W2^T  (fp16, K=128: 8 ksteps) ----
        float acc2[2][4][4];
        #pragma unroll
        for (int i = 0; i < 2; ++i)
            #pragma unroll
            for (int j = 0; j < 4; ++j)
                #pragma unroll
                for (int c = 0; c < 4; ++c) acc2[i][j][c] = 0.f;

        #pragma unroll
        for (int ks = 0; ks < 8; ++ks) {
            uint32_t A[2][4], B[2][4];
            ldsm_x4(A[0], a2b[0] + ks * 32);
            ldsm_x4(A[1], a2b[1] + ks * 32);
            ldsm_x4(B[0], b2b[0] + ks * 32);
            ldsm_x4(B[1], b2b[1] + ks * 32);
            #pragma unroll
            for (int i = 0; i < 2; ++i)
                #pragma unroll
                for (int j = 0; j < 4; ++j)
                    mma_f16(acc2[i][j], A[i], &B[j >> 1][(j & 1) * 2]);
        }

        // ---- Epilogue: direct STG from C2 fragments (+b2) ----
        #pragma unroll
        for (int i = 0; i < 2; ++i) {
            int r = wm * 32 + i * 16 + qr;
            int ge0 = ebase + r;
            int ge1 = ge0 + 8;
            #pragma unroll
            for (int j = 0; j < 4; ++j) {
                int c = wn * 32 + j * 8 + 2 * ql;
                if (ge0 < E)
                    *(float2*)(out + (size_t)ge0 * OUT_DIM + c) =
                        make_float2(acc2[i][j][0] + bb2[j].x, acc2[i][j][1] + bb2[j].y);
                if (ge1 < E)
                    *(float2*)(out + (size_t)ge1 * OUT_DIM + c) =
                        make_float2(acc2[i][j][2] + bb2[j].x, acc2[i][j][3] + bb2[j].y);
            }
        }
        __syncthreads();                       // (E) region0 free for next staging
    }
}

// ---------------------------------------------------------------------------
extern "C" void kernel_launch(void* const* d_in, const int* in_sizes, int n_in,
                              void* d_out, int out_size)
{
    const float* x    = (const float*)d_in[0];
    const int*   eidx = (const int*)  d_in[1];
    const float* ea   = (const float*)d_in[2];
    const float* W1   = (const float*)d_in[3];
    const float* b1   = (const float*)d_in[4];
    const float* W2   = (const float*)d_in[5];
    const float* b2   = (const float*)d_in[6];
    float* out = (float*)d_out;

    int n_nodes = in_sizes[0] / DIM_NODE;
    if (n_nodes > MAX_NODES) n_nodes = MAX_NODES;
    int E = in_sizes[2] / DIM_EDGE;
    int n_tiles = (E + E_TILE - 1) / E_TILE;

    const int smem1 = (64 * 257 + 64 * 68) * 4;       // 83200 B

    cudaFuncSetAttribute(k_precompute, cudaFuncAttributeMaxDynamicSharedMemorySize, smem1);
    cudaFuncSetAttribute(k_edge, cudaFuncAttributeMaxDynamicSharedMemorySize, (int)SMEM_EDGE_BYTES);

    int n_blocks = 148 * 8;
    if (n_blocks > n_tiles) n_blocks = n_tiles;

    k_precompute<<<(n_nodes + 63) / 64, 256, smem1>>>(x, W1, n_nodes);
    k_edge<<<n_blocks, 256, SMEM_EDGE_BYTES>>>(eidx, ea, W1, b1, W2, b2, out, E, n_tiles);
}

// round 8
// speedup vs baseline: 1.4134x; 1.1572x over previous
#include <cuda_runtime.h>
#include <cuda_fp16.h>
#include <cstdint>

#define DIM_NODE 64
#define DIM_EDGE 32
#define D_IN1    160
#define OUT_DIM  64
#define MAX_NODES 50000
#define E_TILE   128
#define NEG_SLOPE 0.01f

// Per-node precomputed partials (fp16): P[n][0:128] = x[n]@W1a^T, P[n][128:256] = x[n]@W1b^T
__device__ __half g_P[(size_t)MAX_NODES * 256];

__device__ __forceinline__ void mma_f16(float* d, const uint32_t* a, const uint32_t* b) {
    asm volatile(
        "mma.sync.aligned.m16n8k16.row.col.f32.f16.f16.f32 "
        "{%0,%1,%2,%3}, {%4,%5,%6,%7}, {%8,%9}, {%0,%1,%2,%3};"
        : "+f"(d[0]), "+f"(d[1]), "+f"(d[2]), "+f"(d[3])
        : "r"(a[0]), "r"(a[1]), "r"(a[2]), "r"(a[3]), "r"(b[0]), "r"(b[1]));
}
__device__ __forceinline__ void ldsm_x4(uint32_t* r, uint32_t addr) {
    asm volatile("ldmatrix.sync.aligned.m8n8.x4.shared.b16 {%0,%1,%2,%3}, [%4];"
        : "=r"(r[0]), "=r"(r[1]), "=r"(r[2]), "=r"(r[3]) : "r"(addr));
}
__device__ __forceinline__ uint32_t smem_u32(const void* p) {
    uint32_t a;
    asm("{ .reg .u64 t; cvta.to.shared.u64 t, %1; cvt.u32.u64 %0, t; }" : "=r"(a) : "l"(p));
    return a;
}
__device__ __forceinline__ uint32_t pack_h2(float a, float b) {
    __half2 h = __floats2half2_rn(a, b);
    return *(uint32_t*)&h;
}
__device__ __forceinline__ float2 h2f2(uint32_t u) {
    __half2 h = *(__half2*)&u;
    return __half22float2(h);
}

// ---------------------------------------------------------------------------
// SMEM layout (BYTE offsets):
//   H   @0     : fp16 [128 rows][136h], row stride 272B, 34816B.
//                 (C1 fp16 staged here by GEMM1; phase B rewrites in place.
//                  EA fp16 [128][40h] stride 80B overlays @0 during staging/GEMM1.)
//   W1C @34816 : fp16 [128][40h] stride 80B, persistent, 10240B
//   W2  @45056 : fp16 [64][136h] stride 272B, persistent, 17408B
//   b1 @62464 (512B), b2 @62976 (256B), src @63232 (512B), dst @63744 (512B)
// ---------------------------------------------------------------------------
#define H_B     0u
#define EA_B    0u
#define W1C_B   34816u
#define W2_B    45056u
#define B1_B    62464u
#define B2_B    62976u
#define SRC_B   63232u
#define DST_B   63744u
#define SMEM_EDGE_BYTES 64256u

// ---------------------------------------------------------------------------
// Kernel 1: node precompute.  64 nodes/block, 256 threads, 8x8 microtile.
// f32 math, fp16 output.
// ---------------------------------------------------------------------------
__global__ __launch_bounds__(256, 2) void k_precompute(
    const float* __restrict__ x, const float* __restrict__ W1, int n_nodes)
{
    extern __shared__ float sm[];
    float* s_w = sm;               // [64][257]
    float* s_x = sm + 64 * 257;    // [64][68]
    const int t = threadIdx.x;

    #pragma unroll
    for (int i = 0; i < 64; ++i) {
        int idx = i * 256 + t;
        int c = idx >> 6, d = idx & 63;
        float v = (c < 128) ? W1[c * D_IN1 + d] : W1[(c - 128) * D_IN1 + 64 + d];
        s_w[d * 257 + c] = v;
    }
    const int node0 = blockIdx.x * 64;
    #pragma unroll
    for (int i = 0; i < 16; ++i) {
        int idx = i * 256 + t;
        int n = idx >> 6, d = idx & 63;
        int gn = node0 + n;
        s_x[n * 68 + d] = (gn < n_nodes) ? x[(size_t)gn * DIM_NODE + d] : 0.f;
    }
    __syncthreads();

    const int n0 = t & 7;
    const int c0 = (t >> 3) * 8;
    float acc[8][8];
    #pragma unroll
    for (int i = 0; i < 8; ++i)
        #pragma unroll
        for (int j = 0; j < 8; ++j) acc[i][j] = 0.f;

    #pragma unroll 4
    for (int d = 0; d < 64; ++d) {
        float xa[8], wb[8];
        #pragma unroll
        for (int i = 0; i < 8; ++i) xa[i] = s_x[(n0 + 8 * i) * 68 + d];
        #pragma unroll
        for (int j = 0; j < 8; ++j) wb[j] = s_w[d * 257 + c0 + j];
        #pragma unroll
        for (int i = 0; i < 8; ++i)
            #pragma unroll
            for (int j = 0; j < 8; ++j)
                acc[i][j] = fmaf(xa[i], wb[j], acc[i][j]);
    }
    #pragma unroll
    for (int i = 0; i < 8; ++i) {
        int gn = node0 + n0 + 8 * i;
        if (gn < n_nodes) {
            uint4* p = (uint4*)((__half*)g_P + (size_t)gn * 256 + c0);
            *p = make_uint4(pack_h2(acc[i][0], acc[i][1]), pack_h2(acc[i][2], acc[i][3]),
                            pack_h2(acc[i][4], acc[i][5]), pack_h2(acc[i][6], acc[i][7]));
        }
    }
}

// ---------------------------------------------------------------------------
// Kernel 2: persistent fp16 mma edge MLP.  128 edges/tile, 8 warps/CTA.
// ---------------------------------------------------------------------------
__global__ __launch_bounds__(256, 2) void k_edge(
    const int*   __restrict__ eidx,
    const float* __restrict__ ea,
    const float* __restrict__ W1,
    const float* __restrict__ b1,
    const float* __restrict__ W2g,
    const float* __restrict__ b2,
    float*       __restrict__ out,
    int E, int n_tiles)
{
    extern __shared__ __align__(16) char smc[];
    const uint32_t sb = smem_u32(smc);
    const int t   = threadIdx.x;
    const int wid = t >> 5;
    const int lid = t & 31;
    const int qr  = lid >> 2;      // 0..7
    const int ql  = lid & 3;       // 0..3
    const int wm  = wid & 3;       // warp M coord (rows of 32)
    const int wn  = wid >> 2;      // warp N coord
    const int lm  = lid & 7;
    const int lq3 = lid >> 3;      // 0..3 (matrix id)
    const int lq4 = lid >> 4;      // 0..1

    int*   s_src = (int*)(smc + SRC_B);
    int*   s_dst = (int*)(smc + DST_B);
    float* s_b1  = (float*)(smc + B1_B);
    float* s_b2  = (float*)(smc + B2_B);

    // ======== CTA prologue: persistent W1C (fp16), W2 (fp16), biases ========
    {   // W1C: row n = t>>1, half hs = t&1 (16 cols)
        int n = t >> 1, hs = t & 1;
        const float4* src = (const float4*)(W1 + n * D_IN1 + 128 + hs * 16);
        float4 v0 = src[0], v1 = src[1], v2 = src[2], v3 = src[3];
        uint4 p0 = make_uint4(pack_h2(v0.x, v0.y), pack_h2(v0.z, v0.w),
                              pack_h2(v1.x, v1.y), pack_h2(v1.z, v1.w));
        uint4 p1 = make_uint4(pack_h2(v2.x, v2.y), pack_h2(v2.z, v2.w),
                              pack_h2(v3.x, v3.y), pack_h2(v3.z, v3.w));
        *(uint4*)(smc + W1C_B + n * 80 + hs * 32)      = p0;
        *(uint4*)(smc + W1C_B + n * 80 + hs * 32 + 16) = p1;
    }
    {   // W2: row n = t>>2, quarter q = t&3 (32 cols)
        int n = t >> 2, q = t & 3;
        const float4* src = (const float4*)(W2g + n * 128 + q * 32);
        #pragma unroll
        for (int s = 0; s < 2; ++s) {
            float4 v0 = src[4 * s + 0], v1 = src[4 * s + 1],
                   v2 = src[4 * s + 2], v3 = src[4 * s + 3];
            uint4 pa = make_uint4(pack_h2(v0.x, v0.y), pack_h2(v0.z, v0.w),
                                  pack_h2(v1.x, v1.y), pack_h2(v1.z, v1.w));
            uint4 pb = make_uint4(pack_h2(v2.x, v2.y), pack_h2(v2.z, v2.w),
                                  pack_h2(v3.x, v3.y), pack_h2(v3.z, v3.w));
            *(uint4*)(smc + W2_B + n * 272 + q * 64 + s * 32)      = pa;
            *(uint4*)(smc + W2_B + n * 272 + q * 64 + s * 32 + 16) = pb;
        }
    }
    if (t < 128)      s_b1[t] = b1[t];
    else if (t < 192) s_b2[t - 128] = b2[t - 128];
    __syncthreads();

    float2 bb2[4];
    #pragma unroll
    for (int j = 0; j < 4; ++j)
        bb2[j] = *(const float2*)(s_b2 + wn * 32 + j * 8 + 2 * ql);
    const float4 bb1 = *(const float4*)(s_b1 + 4 * lid);

    // ---- ldmatrix per-lane base addresses ----
    uint32_t a1b[2], b1b[4], a2b[2], b2b[2];
    #pragma unroll
    for (int i = 0; i < 2; ++i)
        a1b[i] = sb + EA_B + (uint32_t)((wm * 32 + i * 16 + ((lq3 & 1) << 3) + lm) * 80)
               + (uint32_t)((lq3 >> 1) * 16);
    #pragma unroll
    for (int jj = 0; jj < 4; ++jj)
        b1b[jj] = sb + W1C_B + (uint32_t)((wn * 64 + jj * 16 + lq4 * 8 + lm) * 80)
                + (uint32_t)((lq3 & 1) * 16);
    #pragma unroll
    for (int i = 0; i < 2; ++i)
        a2b[i] = sb + H_B + (uint32_t)((wm * 32 + i * 16 + ((lq3 & 1) << 3) + lm) * 272)
               + (uint32_t)((lq3 >> 1) * 16);
    #pragma unroll
    for (int jj = 0; jj < 2; ++jj)
        b2b[jj] = sb + W2_B + (uint32_t)((wn * 32 + jj * 16 + lq4 * 8 + lm) * 272)
                + (uint32_t)((lq3 & 1) * 16);

    // ======== persistent tile loop ========
    for (int tile = blockIdx.x; tile < n_tiles; tile += gridDim.x) {
        const int ebase = tile * E_TILE;

        // ---- stage ea -> fp16 [128][40h] (overlays H region) ----
        {
            int m = t >> 1, hs = t & 1;
            int ge = ebase + m;
            float4 v0, v1, v2, v3;
            if (ge < E) {
                const float4* src = (const float4*)(ea + (size_t)ge * DIM_EDGE + hs * 16);
                v0 = src[0]; v1 = src[1]; v2 = src[2]; v3 = src[3];
            } else {
                v0 = v1 = v2 = v3 = make_float4(0.f, 0.f, 0.f, 0.f);
            }
            uint4 p0 = make_uint4(pack_h2(v0.x, v0.y), pack_h2(v0.z, v0.w),
                                  pack_h2(v1.x, v1.y), pack_h2(v1.z, v1.w));
            uint4 p1 = make_uint4(pack_h2(v2.x, v2.y), pack_h2(v2.z, v2.w),
                                  pack_h2(v3.x, v3.y), pack_h2(v3.z, v3.w));
            *(uint4*)(smc + EA_B + m * 80 + hs * 32)      = p0;
            *(uint4*)(smc + EA_B + m * 80 + hs * 32 + 16) = p1;
        }
        if (t < 128) {
            int e = ebase + t;
            s_src[t] = (e < E) ? eidx[e] : 0;
        } else {
            int e = ebase + (t - 128);
            s_dst[t - 128] = (e < E) ? eidx[E + e] : 0;
        }
        __syncthreads();                       // (A)

        // ---- GEMM1: C1[128x128] = ea @ W1c^T  (fp16, K=32: 2 ksteps) ----
        float acc1[2][8][4];
        #pragma unroll
        for (int i = 0; i < 2; ++i)
            #pragma unroll
            for (int j = 0; j < 8; ++j)
                #pragma unroll
                for (int c = 0; c < 4; ++c) acc1[i][j][c] = 0.f;

        #pragma unroll
        for (int ks = 0; ks < 2; ++ks) {
            uint32_t A[2][4], B[4][4];
            ldsm_x4(A[0], a1b[0] + ks * 32);
            ldsm_x4(A[1], a1b[1] + ks * 32);
            #pragma unroll
            for (int jj = 0; jj < 4; ++jj)
                ldsm_x4(B[jj], b1b[jj] + ks * 32);
            #pragma unroll
            for (int i = 0; i < 2; ++i)
                #pragma unroll
                for (int j = 0; j < 8; ++j)
                    mma_f16(acc1[i][j], A[i], &B[j >> 1][(j & 1) * 2]);
        }
        __syncthreads();                       // (B) EA reads done; region becomes C1/h

        // ---- STS C1 (fp16) -> H [128][136h], stride 272B ----
        #pragma unroll
        for (int i = 0; i < 2; ++i) {
            int r = wm * 32 + i * 16 + qr;
            #pragma unroll
            for (int j = 0; j < 8; ++j) {
                int c = wn * 64 + j * 8 + 2 * ql;
                *(uint32_t*)(smc + H_B + r * 272 + 2 * c) =
                    pack_h2(acc1[i][j][0], acc1[i][j][1]);
                *(uint32_t*)(smc + H_B + (r + 8) * 272 + 2 * c) =
                    pack_h2(acc1[i][j][2], acc1[i][j][3]);
            }
        }
        __syncthreads();                       // (C)

        // ---- Phase B: h = fp16(leaky(C1 + P_src + P_dst + b1)), in place ----
        {
            const int m0 = wid * 16;
            #pragma unroll
            for (int g = 0; g < 16; g += 4) {
                uint2 us[4], ud[4], hc[4];
                #pragma unroll
                for (int r = 0; r < 4; ++r) {
                    int m = m0 + g + r;
                    us[r] = *(const uint2*)((const __half*)g_P + (size_t)s_src[m] * 256 + 4 * lid);
                    ud[r] = *(const uint2*)((const __half*)g_P + (size_t)s_dst[m] * 256 + 128 + 4 * lid);
                }
                #pragma unroll
                for (int r = 0; r < 4; ++r)
                    hc[r] = *(const uint2*)(smc + H_B + (m0 + g + r) * 272 + 8 * lid);
                #pragma unroll
                for (int r = 0; r < 4; ++r) {
                    float2 c01 = h2f2(hc[r].x), c23 = h2f2(hc[r].y);
                    float2 s01 = h2f2(us[r].x), s23 = h2f2(us[r].y);
                    float2 d01 = h2f2(ud[r].x), d23 = h2f2(ud[r].y);
                    float h0 = c01.x + s01.x + d01.x + bb1.x;
                    float h1 = c01.y + s01.y + d01.y + bb1.y;
                    float h2 = c23.x + s23.x + d23.x + bb1.z;
                    float h3 = c23.y + s23.y + d23.y + bb1.w;
                    h0 = (h0 >= 0.f) ? h0 : NEG_SLOPE * h0;
                    h1 = (h1 >= 0.f) ? h1 : NEG_SLOPE * h1;
                    h2 = (h2 >= 0.f) ? h2 : NEG_SLOPE * h2;
                    h3 = (h3 >= 0.f) ? h3 : NEG_SLOPE * h3;
                    *(uint2*)(smc + H_B + (m0 + g + r) * 272 + 8 * lid) =
                        make_uint2(pack_h2(h0, h1), pack_h2(h2, h3));
                }
            }
        }
        __syncthreads();                       // (D)

        // ---- GEMM2: C2[128x64] = h @ W2^T  (fp16, K=128: 8 ksteps) ----
        float acc2[2][4][4];
        #pragma unroll
        for (int i = 0; i < 2; ++i)
            #pragma unroll
            for (int j = 0; j < 4; ++j)
                #pragma unroll
                for (int c = 0; c < 4; ++c) acc2[i][j][c] = 0.f;

        #pragma unroll
        for (int ks = 0; ks < 8; ++ks) {
            uint32_t A[2][4], B[2][4];
            ldsm_x4(A[0], a2b[0] + ks * 32);
            ldsm_x4(A[1], a2b[1] + ks * 32);
            ldsm_x4(B[0], b2b[0] + ks * 32);
            ldsm_x4(B[1], b2b[1] + ks * 32);
            #pragma unroll
            for (int i = 0; i < 2; ++i)
                #pragma unroll
                for (int j = 0; j < 4; ++j)
                    mma_f16(acc2[i][j], A[i], &B[j >> 1][(j & 1) * 2]);
        }

        // ---- Epilogue: direct STG from C2 fragments (+b2) ----
        #pragma unroll
        for (int i = 0; i < 2; ++i) {
            int r = wm * 32 + i * 16 + qr;
            int ge0 = ebase + r;
            int ge1 = ge0 + 8;
            #pragma unroll
            for (int j = 0; j < 4; ++j) {
                int c = wn * 32 + j * 8 + 2 * ql;
                if (ge0 < E)
                    *(float2*)(out + (size_t)ge0 * OUT_DIM + c) =
                        make_float2(acc2[i][j][0] + bb2[j].x, acc2[i][j][1] + bb2[j].y);
                if (ge1 < E)
                    *(float2*)(out + (size_t)ge1 * OUT_DIM + c) =
                        make_float2(acc2[i][j][2] + bb2[j].x, acc2[i][j][3] + bb2[j].y);
            }
        }
        __syncthreads();                       // (E) H region free for next staging
    }
}

// ---------------------------------------------------------------------------
extern "C" void kernel_launch(void* const* d_in, const int* in_sizes, int n_in,
                              void* d_out, int out_size)
{
    const float* x    = (const float*)d_in[0];
    const int*   eidx = (const int*)  d_in[1];
    const float* ea   = (const float*)d_in[2];
    const float* W1   = (const float*)d_in[3];
    const float* b1   = (const float*)d_in[4];
    const float* W2   = (const float*)d_in[5];
    const float* b2   = (const float*)d_in[6];
    float* out = (float*)d_out;

    int n_nodes = in_sizes[0] / DIM_NODE;
    if (n_nodes > MAX_NODES) n_nodes = MAX_NODES;
    int E = in_sizes[2] / DIM_EDGE;
    int n_tiles = (E + E_TILE - 1) / E_TILE;

    const int smem1 = (64 * 257 + 64 * 68) * 4;       // 83200 B

    cudaFuncSetAttribute(k_precompute, cudaFuncAttributeMaxDynamicSharedMemorySize, smem1);
    cudaFuncSetAttribute(k_edge, cudaFuncAttributeMaxDynamicSharedMemorySize, (int)SMEM_EDGE_BYTES);

    int n_blocks = 148 * 8;
    if (n_blocks > n_tiles) n_blocks = n_tiles;

    k_precompute<<<(n_nodes + 63) / 64, 256, smem1>>>(x, W1, n_nodes);
    k_edge<<<n_blocks, 256, SMEM_EDGE_BYTES>>>(eidx, ea, W1, b1, W2, b2, out, E, n_tiles);
}

// round 10
// speedup vs baseline: 1.5745x; 1.1140x over previous
#include <cuda_runtime.h>
#include <cuda_fp16.h>
#include <cstdint>

#define DIM_NODE 64
#define DIM_EDGE 32
#define D_IN1    160
#define OUT_DIM  64
#define MAX_NODES 50000
#define E_TILE   128
#define NEG_SLOPE 0.01f

// Per-node precomputed partials (fp16): P[n][0:128] = x[n]@W1a^T, P[n][128:256] = x[n]@W1b^T
__device__ __half g_P[(size_t)MAX_NODES * 256];

__device__ __forceinline__ void mma_f16(float* d, const uint32_t* a, const uint32_t* b) {
    asm volatile(
        "mma.sync.aligned.m16n8k16.row.col.f32.f16.f16.f32 "
        "{%0,%1,%2,%3}, {%4,%5,%6,%7}, {%8,%9}, {%0,%1,%2,%3};"
        : "+f"(d[0]), "+f"(d[1]), "+f"(d[2]), "+f"(d[3])
        : "r"(a[0]), "r"(a[1]), "r"(a[2]), "r"(a[3]), "r"(b[0]), "r"(b[1]));
}
__device__ __forceinline__ void ldsm_x4(uint32_t* r, uint32_t addr) {
    asm volatile("ldmatrix.sync.aligned.m8n8.x4.shared.b16 {%0,%1,%2,%3}, [%4];"
        : "=r"(r[0]), "=r"(r[1]), "=r"(r[2]), "=r"(r[3]) : "r"(addr));
}
__device__ __forceinline__ uint32_t smem_u32(const void* p) {
    uint32_t a;
    asm("{ .reg .u64 t; cvta.to.shared.u64 t, %1; cvt.u32.u64 %0, t; }" : "=r"(a) : "l"(p));
    return a;
}
__device__ __forceinline__ uint32_t pack_h2(float a, float b) {
    __half2 h = __floats2half2_rn(a, b);
    return *(uint32_t*)&h;
}
__device__ __forceinline__ float2 h2f2(uint32_t u) {
    __half2 h = *(__half2*)&u;
    return __half22float2(h);
}

// ===========================================================================
// Kernel 1: node precompute via fp16 mma.  128 nodes/CTA, 8 warps.
// P[128 x 256] computed as two N=128 halves.
// SMEM (bytes): XT @0 [128][144B], V @18432 [256][144B], PH @55296 [128][272B]
// ===========================================================================
#define PRE_XT_B  0u
#define PRE_V_B   18432u
#define PRE_PH_B  55296u
#define PRE_SMEM  90112u

__global__ __launch_bounds__(256, 2) void k_precompute(
    const float* __restrict__ x, const float* __restrict__ W1, int n_nodes)
{
    extern __shared__ __align__(16) char smc[];
    const uint32_t sb = smem_u32(smc);
    const int t   = threadIdx.x;
    const int wid = t >> 5;
    const int lid = t & 31;
    const int qr  = lid >> 2;
    const int ql  = lid & 3;
    const int wm  = wid & 3;       // rows of 32
    const int wn  = wid >> 2;      // cols of 64 (within a 128 half)
    const int lm  = lid & 7;
    const int lq3 = lid >> 3;      // 0..3
    const int lq4 = lid >> 4;      // 0..1
    const int node0 = blockIdx.x * 128;

    // ---- stage V (combined 256x64 weight) as fp16 [256][144B] ----
    {
        int c = t;                                 // 0..255
        const float* src = (c < 128) ? (W1 + c * D_IN1) : (W1 + (c - 128) * D_IN1 + 64);
        #pragma unroll
        for (int s = 0; s < 4; ++s) {
            float4 v0 = *(const float4*)(src + s * 16 + 0);
            float4 v1 = *(const float4*)(src + s * 16 + 4);
            float4 v2 = *(const float4*)(src + s * 16 + 8);
            float4 v3 = *(const float4*)(src + s * 16 + 12);
            uint4 pa = make_uint4(pack_h2(v0.x, v0.y), pack_h2(v0.z, v0.w),
                                  pack_h2(v1.x, v1.y), pack_h2(v1.z, v1.w));
            uint4 pb = make_uint4(pack_h2(v2.x, v2.y), pack_h2(v2.z, v2.w),
                                  pack_h2(v3.x, v3.y), pack_h2(v3.z, v3.w));
            *(uint4*)(smc + PRE_V_B + c * 144 + s * 32)      = pa;
            *(uint4*)(smc + PRE_V_B + c * 144 + s * 32 + 16) = pb;
        }
    }
    // ---- stage x tile as fp16 [128][144B] : 64 floats/row, 32 per thread ----
    {
        int m = t >> 1, hs = t & 1;
        int gn = node0 + m;
        #pragma unroll
        for (int s = 0; s < 2; ++s) {
            float4 v0, v1, v2, v3;
            if (gn < n_nodes) {
                const float4* src = (const float4*)(x + (size_t)gn * DIM_NODE + hs * 32 + s * 16);
                v0 = src[0]; v1 = src[1]; v2 = src[2]; v3 = src[3];
            } else {
                v0 = v1 = v2 = v3 = make_float4(0.f, 0.f, 0.f, 0.f);
            }
            uint4 pa = make_uint4(pack_h2(v0.x, v0.y), pack_h2(v0.z, v0.w),
                                  pack_h2(v1.x, v1.y), pack_h2(v1.z, v1.w));
            uint4 pb = make_uint4(pack_h2(v2.x, v2.y), pack_h2(v2.z, v2.w),
                                  pack_h2(v3.x, v3.y), pack_h2(v3.z, v3.w));
            *(uint4*)(smc + PRE_XT_B + m * 144 + hs * 64 + s * 32)      = pa;
            *(uint4*)(smc + PRE_XT_B + m * 144 + hs * 64 + s * 32 + 16) = pb;
        }
    }
    __syncthreads();

    // ldmatrix bases
    uint32_t ab[2];
    #pragma unroll
    for (int i = 0; i < 2; ++i)
        ab[i] = sb + PRE_XT_B + (uint32_t)((wm * 32 + i * 16 + ((lq3 & 1) << 3) + lm) * 144)
              + (uint32_t)((lq3 >> 1) * 16);

    #pragma unroll
    for (int nh = 0; nh < 2; ++nh) {
        if (nh) __syncthreads();               // PH drained by previous STG

        float acc[2][8][4];
        #pragma unroll
        for (int i = 0; i < 2; ++i)
            #pragma unroll
            for (int j = 0; j < 8; ++j)
                #pragma unroll
                for (int c = 0; c < 4; ++c) acc[i][j][c] = 0.f;

        #pragma unroll
        for (int ks = 0; ks < 4; ++ks) {
            uint32_t A[2][4], B[4][4];
            ldsm_x4(A[0], ab[0] + ks * 32);
            ldsm_x4(A[1], ab[1] + ks * 32);
            #pragma unroll
            for (int jj = 0; jj < 4; ++jj) {
                int n = nh * 128 + wn * 64 + jj * 16 + lq4 * 8 + lm;
                ldsm_x4(B[jj], sb + PRE_V_B + (uint32_t)(n * 144)
                               + (uint32_t)((lq3 & 1) * 16) + ks * 32);
            }
            #pragma unroll
            for (int i = 0; i < 2; ++i)
                #pragma unroll
                for (int j = 0; j < 8; ++j)
                    mma_f16(acc[i][j], A[i], &B[j >> 1][(j & 1) * 2]);
        }

        // STS fragments -> PH [128][272B] fp16
        #pragma unroll
        for (int i = 0; i < 2; ++i) {
            int r = wm * 32 + i * 16 + qr;
            #pragma unroll
            for (int j = 0; j < 8; ++j) {
                int c = wn * 64 + j * 8 + 2 * ql;
                *(uint32_t*)(smc + PRE_PH_B + r * 272 + 2 * c) =
                    pack_h2(acc[i][j][0], acc[i][j][1]);
                *(uint32_t*)(smc + PRE_PH_B + (r + 8) * 272 + 2 * c) =
                    pack_h2(acc[i][j][2], acc[i][j][3]);
            }
        }
        __syncthreads();

        // STG: copy PH -> g_P[node][nh*128 ..]
        {
            int m = t >> 1, hs = t & 1;
            int gn = node0 + m;
            if (gn < n_nodes) {
                const uint4* srcp = (const uint4*)(smc + PRE_PH_B + m * 272 + hs * 128);
                uint4* dstp = (uint4*)((__half*)g_P + (size_t)gn * 256 + nh * 128 + hs * 64);
                #pragma unroll
                for (int s = 0; s < 8; ++s) dstp[s] = srcp[s];
            }
        }
    }
}

// ---------------------------------------------------------------------------
// SMEM layout for k_edge (BYTE offsets) — unchanged from round 8.
// ---------------------------------------------------------------------------
#define H_B     0u
#define EA_B    0u
#define W1C_B   34816u
#define W2_B    45056u
#define B1_B    62464u
#define B2_B    62976u
#define SRC_B   63232u
#define DST_B   63744u
#define SMEM_EDGE_BYTES 64256u

// ---------------------------------------------------------------------------
// Kernel 2: persistent fp16 mma edge MLP.  128 edges/tile, 8 warps/CTA.
// ---------------------------------------------------------------------------
__global__ __launch_bounds__(256, 2) void k_edge(
    const int*   __restrict__ eidx,
    const float* __restrict__ ea,
    const float* __restrict__ W1,
    const float* __restrict__ b1,
    const float* __restrict__ W2g,
    const float* __restrict__ b2,
    float*       __restrict__ out,
    int E, int n_tiles)
{
    extern __shared__ __align__(16) char smc[];
    const uint32_t sb = smem_u32(smc);
    const int t   = threadIdx.x;
    const int wid = t >> 5;
    const int lid = t & 31;
    const int qr  = lid >> 2;
    const int ql  = lid & 3;
    const int wm  = wid & 3;
    const int wn  = wid >> 2;
    const int lm  = lid & 7;
    const int lq3 = lid >> 3;
    const int lq4 = lid >> 4;

    int*   s_src = (int*)(smc + SRC_B);
    int*   s_dst = (int*)(smc + DST_B);
    float* s_b1  = (float*)(smc + B1_B);
    float* s_b2  = (float*)(smc + B2_B);

    // ======== CTA prologue: persistent W1C (fp16), W2 (fp16), biases ========
    {
        int n = t >> 1, hs = t & 1;
        const float4* src = (const float4*)(W1 + n * D_IN1 + 128 + hs * 16);
        float4 v0 = src[0], v1 = src[1], v2 = src[2], v3 = src[3];
        uint4 p0 = make_uint4(pack_h2(v0.x, v0.y), pack_h2(v0.z, v0.w),
                              pack_h2(v1.x, v1.y), pack_h2(v1.z, v1.w));
        uint4 p1 = make_uint4(pack_h2(v2.x, v2.y), pack_h2(v2.z, v2.w),
                              pack_h2(v3.x, v3.y), pack_h2(v3.z, v3.w));
        *(uint4*)(smc + W1C_B + n * 80 + hs * 32)      = p0;
        *(uint4*)(smc + W1C_B + n * 80 + hs * 32 + 16) = p1;
    }
    {
        int n = t >> 2, q = t & 3;
        const float4* src = (const float4*)(W2g + n * 128 + q * 32);
        #pragma unroll
        for (int s = 0; s < 2; ++s) {
            float4 v0 = src[4 * s + 0], v1 = src[4 * s + 1],
                   v2 = src[4 * s + 2], v3 = src[4 * s + 3];
            uint4 pa = make_uint4(pack_h2(v0.x, v0.y), pack_h2(v0.z, v0.w),
                                  pack_h2(v1.x, v1.y), pack_h2(v1.z, v1.w));
            uint4 pb = make_uint4(pack_h2(v2.x, v2.y), pack_h2(v2.z, v2.w),
                                  pack_h2(v3.x, v3.y), pack_h2(v3.z, v3.w));
            *(uint4*)(smc + W2_B + n * 272 + q * 64 + s * 32)      = pa;
            *(uint4*)(smc + W2_B + n * 272 + q * 64 + s * 32 + 16) = pb;
        }
    }
    if (t < 128)      s_b1[t] = b1[t];
    else if (t < 192) s_b2[t - 128] = b2[t - 128];
    __syncthreads();

    float2 bb2[4];
    #pragma unroll
    for (int j = 0; j < 4; ++j)
        bb2[j] = *(const float2*)(s_b2 + wn * 32 + j * 8 + 2 * ql);
    const float4 bb1 = *(const float4*)(s_b1 + 4 * lid);

    uint32_t a1b[2], b1b[4], a2b[2], b2b[2];
    #pragma unroll
    for (int i = 0; i < 2; ++i)
        a1b[i] = sb + EA_B + (uint32_t)((wm * 32 + i * 16 + ((lq3 & 1) << 3) + lm) * 80)
               + (uint32_t)((lq3 >> 1) * 16);
    #pragma unroll
    for (int jj = 0; jj < 4; ++jj)
        b1b[jj] = sb + W1C_B + (uint32_t)((wn * 64 + jj * 16 + lq4 * 8 + lm) * 80)
                + (uint32_t)((lq3 & 1) * 16);
    #pragma unroll
    for (int i = 0; i < 2; ++i)
        a2b[i] = sb + H_B + (uint32_t)((wm * 32 + i * 16 + ((lq3 & 1) << 3) + lm) * 272)
               + (uint32_t)((lq3 >> 1) * 16);
    #pragma unroll
    for (int jj = 0; jj < 2; ++jj)
        b2b[jj] = sb + W2_B + (uint32_t)((wn * 32 + jj * 16 + lq4 * 8 + lm) * 272)
                + (uint32_t)((lq3 & 1) * 16);

    for (int tile = blockIdx.x; tile < n_tiles; tile += gridDim.x) {
        const int ebase = tile * E_TILE;

        {
            int m = t >> 1, hs = t & 1;
            int ge = ebase + m;
            float4 v0, v1, v2, v3;
            if (ge < E) {
                const float4* src = (const float4*)(ea + (size_t)ge * DIM_EDGE + hs * 16);
                v0 = src[0]; v1 = src[1]; v2 = src[2]; v3 = src[3];
            } else {
                v0 = v1 = v2 = v3 = make_float4(0.f, 0.f, 0.f, 0.f);
            }
            uint4 p0 = make_uint4(pack_h2(v0.x, v0.y), pack_h2(v0.z, v0.w),
                                  pack_h2(v1.x, v1.y), pack_h2(v1.z, v1.w));
            uint4 p1 = make_uint4(pack_h2(v2.x, v2.y), pack_h2(v2.z, v2.w),
                                  pack_h2(v3.x, v3.y), pack_h2(v3.z, v3.w));
            *(uint4*)(smc + EA_B + m * 80 + hs * 32)      = p0;
            *(uint4*)(smc + EA_B + m * 80 + hs * 32 + 16) = p1;
        }
        if (t < 128) {
            int e = ebase + t;
            s_src[t] = (e < E) ? eidx[e] : 0;
        } else {
            int e = ebase + (t - 128);
            s_dst[t - 128] = (e < E) ? eidx[E + e] : 0;
        }
        __syncthreads();                       // (A)

        float acc1[2][8][4];
        #pragma unroll
        for (int i = 0; i < 2; ++i)
            #pragma unroll
            for (int j = 0; j < 8; ++j)
                #pragma unroll
                for (int c = 0; c < 4; ++c) acc1[i][j][c] = 0.f;

        #pragma unroll
        for (int ks = 0; ks < 2; ++ks) {
            uint32_t A[2][4], B[4][4];
            ldsm_x4(A[0], a1b[0] + ks * 32);
            ldsm_x4(A[1], a1b[1] + ks * 32);
            #pragma unroll
            for (int jj = 0; jj < 4; ++jj)
                ldsm_x4(B[jj], b1b[jj] + ks * 32);
            #pragma unroll
            for (int i = 0; i < 2; ++i)
                #pragma unroll
                for (int j = 0; j < 8; ++j)
                    mma_f16(acc1[i][j], A[i], &B[j >> 1][(j & 1) * 2]);
        }
        __syncthreads();                       // (B)

        #pragma unroll
        for (int i = 0; i < 2; ++i) {
            int r = wm * 32 + i * 16 + qr;
            #pragma unroll
            for (int j = 0; j < 8; ++j) {
                int c = wn * 64 + j * 8 + 2 * ql;
                *(uint32_t*)(smc + H_B + r * 272 + 2 * c) =
                    pack_h2(acc1[i][j][0], acc1[i][j][1]);
                *(uint32_t*)(smc + H_B + (r + 8) * 272 + 2 * c) =
                    pack_h2(acc1[i][j][2], acc1[i][j][3]);
            }
        }
        __syncthreads();                       // (C)

        {
            const int m0 = wid * 16;
            #pragma unroll
            for (int g = 0; g < 16; g += 4) {
                uint2 us[4], ud[4], hc[4];
                #pragma unroll
                for (int r = 0; r < 4; ++r) {
                    int m = m0 + g + r;
                    us[r] = *(const uint2*)((const __half*)g_P + (size_t)s_src[m] * 256 + 4 * lid);
                    ud[r] = *(const uint2*)((const __half*)g_P + (size_t)s_dst[m] * 256 + 128 + 4 * lid);
                }
                #pragma unroll
                for (int r = 0; r < 4; ++r)
                    hc[r] = *(const uint2*)(smc + H_B + (m0 + g + r) * 272 + 8 * lid);
                #pragma unroll
                for (int r = 0; r < 4; ++r) {
                    float2 c01 = h2f2(hc[r].x), c23 = h2f2(hc[r].y);
                    float2 s01 = h2f2(us[r].x), s23 = h2f2(us[r].y);
                    float2 d01 = h2f2(ud[r].x), d23 = h2f2(ud[r].y);
                    float h0 = c01.x + s01.x + d01.x + bb1.x;
                    float h1 = c01.y + s01.y + d01.y + bb1.y;
                    float h2 = c23.x + s23.x + d23.x + bb1.z;
                    float h3 = c23.y + s23.y + d23.y + bb1.w;
                    h0 = (h0 >= 0.f) ? h0 : NEG_SLOPE * h0;
                    h1 = (h1 >= 0.f) ? h1 : NEG_SLOPE * h1;
                    h2 = (h2 >= 0.f) ? h2 : NEG_SLOPE * h2;
                    h3 = (h3 >= 0.f) ? h3 : NEG_SLOPE * h3;
                    *(uint2*)(smc + H_B + (m0 + g + r) * 272 + 8 * lid) =
                        make_uint2(pack_h2(h0, h1), pack_h2(h2, h3));
                }
            }
        }
        __syncthreads();                       // (D)

        float acc2[2][4][4];
        #pragma unroll
        for (int i = 0; i < 2; ++i)
            #pragma unroll
            for (int j = 0; j < 4; ++j)
                #pragma unroll
                for (int c = 0; c < 4; ++c) acc2[i][j][c] = 0.f;

        #pragma unroll
        for (int ks = 0; ks < 8; ++ks) {
            uint32_t A[2][4], B[2][4];
            ldsm_x4(A[0], a2b[0] + ks * 32);
            ldsm_x4(A[1], a2b[1] + ks * 32);
            ldsm_x4(B[0], b2b[0] + ks * 32);
            ldsm_x4(B[1], b2b[1] + ks * 32);
            #pragma unroll
            for (int i = 0; i < 2; ++i)
                #pragma unroll
                for (int j = 0; j < 4; ++j)
                    mma_f16(acc2[i][j], A[i], &B[j >> 1][(j & 1) * 2]);
        }

        #pragma unroll
        for (int i = 0; i < 2; ++i) {
            int r = wm * 32 + i * 16 + qr;
            int ge0 = ebase + r;
            int ge1 = ge0 + 8;
            #pragma unroll
            for (int j = 0; j < 4; ++j) {
                int c = wn * 32 + j * 8 + 2 * ql;
                if (ge0 < E)
                    *(float2*)(out + (size_t)ge0 * OUT_DIM + c) =
                        make_float2(acc2[i][j][0] + bb2[j].x, acc2[i][j][1] + bb2[j].y);
                if (ge1 < E)
                    *(float2*)(out + (size_t)ge1 * OUT_DIM + c) =
                        make_float2(acc2[i][j][2] + bb2[j].x, acc2[i][j][3] + bb2[j].y);
            }
        }
        __syncthreads();                       // (E)
    }
}

// ---------------------------------------------------------------------------
extern "C" void kernel_launch(void* const* d_in, const int* in_sizes, int n_in,
                              void* d_out, int out_size)
{
    const float* x    = (const float*)d_in[0];
    const int*   eidx = (const int*)  d_in[1];
    const float* ea   = (const float*)d_in[2];
    const float* W1   = (const float*)d_in[3];
    const float* b1   = (const float*)d_in[4];
    const float* W2   = (const float*)d_in[5];
    const float* b2   = (const float*)d_in[6];
    float* out = (float*)d_out;

    int n_nodes = in_sizes[0] / DIM_NODE;
    if (n_nodes > MAX_NODES) n_nodes = MAX_NODES;
    int E = in_sizes[2] / DIM_EDGE;
    int n_tiles = (E + E_TILE - 1) / E_TILE;

    cudaFuncSetAttribute(k_precompute, cudaFuncAttributeMaxDynamicSharedMemorySize, (int)PRE_SMEM);
    cudaFuncSetAttribute(k_edge, cudaFuncAttributeMaxDynamicSharedMemorySize, (int)SMEM_EDGE_BYTES);

    int n_blocks = 148 * 8;
    if (n_blocks > n_tiles) n_blocks = n_tiles;

    k_precompute<<<(n_nodes + 127) / 128, 256, PRE_SMEM>>>(x, W1, n_nodes);
    k_edge<<<n_blocks, 256, SMEM_EDGE_BYTES>>>(eidx, ea, W1, b1, W2, b2, out, E, n_tiles);
}

// round 11
// speedup vs baseline: 1.7081x; 1.0848x over previous
#include <cuda_runtime.h>
#include <cuda_fp16.h>
#include <cstdint>

#define DIM_NODE 64
#define DIM_EDGE 32
#define D_IN1    160
#define OUT_DIM  64
#define MAX_NODES 50000
#define E_TILE   128
#define NEG_SLOPE 0.01f

// Per-node precomputed partials (fp16): P[n][0:128] = x[n]@W1a^T, P[n][128:256] = x[n]@W1b^T
__device__ __half g_P[(size_t)MAX_NODES * 256];

__device__ __forceinline__ void mma_f16(float* d, const uint32_t* a, const uint32_t* b) {
    asm volatile(
        "mma.sync.aligned.m16n8k16.row.col.f32.f16.f16.f32 "
        "{%0,%1,%2,%3}, {%4,%5,%6,%7}, {%8,%9}, {%0,%1,%2,%3};"
        : "+f"(d[0]), "+f"(d[1]), "+f"(d[2]), "+f"(d[3])
        : "r"(a[0]), "r"(a[1]), "r"(a[2]), "r"(a[3]), "r"(b[0]), "r"(b[1]));
}
__device__ __forceinline__ void ldsm_x4(uint32_t* r, uint32_t addr) {
    asm volatile("ldmatrix.sync.aligned.m8n8.x4.shared.b16 {%0,%1,%2,%3}, [%4];"
        : "=r"(r[0]), "=r"(r[1]), "=r"(r[2]), "=r"(r[3]) : "r"(addr));
}
__device__ __forceinline__ uint32_t smem_u32(const void* p) {
    uint32_t a;
    asm("{ .reg .u64 t; cvta.to.shared.u64 t, %1; cvt.u32.u64 %0, t; }" : "=r"(a) : "l"(p));
    return a;
}
__device__ __forceinline__ uint32_t pack_h2(float a, float b) {
    __half2 h = __floats2half2_rn(a, b);
    return *(uint32_t*)&h;
}
__device__ __forceinline__ float2 h2f2(uint32_t u) {
    __half2 h = *(__half2*)&u;
    return __half22float2(h);
}

// ===========================================================================
// Kernel 1: node precompute via fp16 mma (unchanged from round 10).
// SMEM (bytes): XT @0 [128][144B], V @18432 [256][144B], PH @55296 [128][272B]
// ===========================================================================
#define PRE_XT_B  0u
#define PRE_V_B   18432u
#define PRE_PH_B  55296u
#define PRE_SMEM  90112u

__global__ __launch_bounds__(256, 2) void k_precompute(
    const float* __restrict__ x, const float* __restrict__ W1, int n_nodes)
{
    extern __shared__ __align__(16) char smc[];
    const uint32_t sb = smem_u32(smc);
    const int t   = threadIdx.x;
    const int wid = t >> 5;
    const int lid = t & 31;
    const int qr  = lid >> 2;
    const int ql  = lid & 3;
    const int wm  = wid & 3;
    const int wn  = wid >> 2;
    const int lm  = lid & 7;
    const int lq3 = lid >> 3;
    const int lq4 = lid >> 4;
    const int node0 = blockIdx.x * 128;

    {
        int c = t;
        const float* src = (c < 128) ? (W1 + c * D_IN1) : (W1 + (c - 128) * D_IN1 + 64);
        #pragma unroll
        for (int s = 0; s < 4; ++s) {
            float4 v0 = *(const float4*)(src + s * 16 + 0);
            float4 v1 = *(const float4*)(src + s * 16 + 4);
            float4 v2 = *(const float4*)(src + s * 16 + 8);
            float4 v3 = *(const float4*)(src + s * 16 + 12);
            uint4 pa = make_uint4(pack_h2(v0.x, v0.y), pack_h2(v0.z, v0.w),
                                  pack_h2(v1.x, v1.y), pack_h2(v1.z, v1.w));
            uint4 pb = make_uint4(pack_h2(v2.x, v2.y), pack_h2(v2.z, v2.w),
                                  pack_h2(v3.x, v3.y), pack_h2(v3.z, v3.w));
            *(uint4*)(smc + PRE_V_B + c * 144 + s * 32)      = pa;
            *(uint4*)(smc + PRE_V_B + c * 144 + s * 32 + 16) = pb;
        }
    }
    {
        int m = t >> 1, hs = t & 1;
        int gn = node0 + m;
        #pragma unroll
        for (int s = 0; s < 2; ++s) {
            float4 v0, v1, v2, v3;
            if (gn < n_nodes) {
                const float4* src = (const float4*)(x + (size_t)gn * DIM_NODE + hs * 32 + s * 16);
                v0 = src[0]; v1 = src[1]; v2 = src[2]; v3 = src[3];
            } else {
                v0 = v1 = v2 = v3 = make_float4(0.f, 0.f, 0.f, 0.f);
            }
            uint4 pa = make_uint4(pack_h2(v0.x, v0.y), pack_h2(v0.z, v0.w),
                                  pack_h2(v1.x, v1.y), pack_h2(v1.z, v1.w));
            uint4 pb = make_uint4(pack_h2(v2.x, v2.y), pack_h2(v2.z, v2.w),
                                  pack_h2(v3.x, v3.y), pack_h2(v3.z, v3.w));
            *(uint4*)(smc + PRE_XT_B + m * 144 + hs * 64 + s * 32)      = pa;
            *(uint4*)(smc + PRE_XT_B + m * 144 + hs * 64 + s * 32 + 16) = pb;
        }
    }
    __syncthreads();

    uint32_t ab[2];
    #pragma unroll
    for (int i = 0; i < 2; ++i)
        ab[i] = sb + PRE_XT_B + (uint32_t)((wm * 32 + i * 16 + ((lq3 & 1) << 3) + lm) * 144)
              + (uint32_t)((lq3 >> 1) * 16);

    #pragma unroll
    for (int nh = 0; nh < 2; ++nh) {
        if (nh) __syncthreads();

        float acc[2][8][4];
        #pragma unroll
        for (int i = 0; i < 2; ++i)
            #pragma unroll
            for (int j = 0; j < 8; ++j)
                #pragma unroll
                for (int c = 0; c < 4; ++c) acc[i][j][c] = 0.f;

        #pragma unroll
        for (int ks = 0; ks < 4; ++ks) {
            uint32_t A[2][4], B[4][4];
            ldsm_x4(A[0], ab[0] + ks * 32);
            ldsm_x4(A[1], ab[1] + ks * 32);
            #pragma unroll
            for (int jj = 0; jj < 4; ++jj) {
                int n = nh * 128 + wn * 64 + jj * 16 + lq4 * 8 + lm;
                ldsm_x4(B[jj], sb + PRE_V_B + (uint32_t)(n * 144)
                               + (uint32_t)((lq3 & 1) * 16) + ks * 32);
            }
            #pragma unroll
            for (int i = 0; i < 2; ++i)
                #pragma unroll
                for (int j = 0; j < 8; ++j)
                    mma_f16(acc[i][j], A[i], &B[j >> 1][(j & 1) * 2]);
        }

        #pragma unroll
        for (int i = 0; i < 2; ++i) {
            int r = wm * 32 + i * 16 + qr;
            #pragma unroll
            for (int j = 0; j < 8; ++j) {
                int c = wn * 64 + j * 8 + 2 * ql;
                *(uint32_t*)(smc + PRE_PH_B + r * 272 + 2 * c) =
                    pack_h2(acc[i][j][0], acc[i][j][1]);
                *(uint32_t*)(smc + PRE_PH_B + (r + 8) * 272 + 2 * c) =
                    pack_h2(acc[i][j][2], acc[i][j][3]);
            }
        }
        __syncthreads();

        {
            int m = t >> 1, hs = t & 1;
            int gn = node0 + m;
            if (gn < n_nodes) {
                const uint4* srcp = (const uint4*)(smc + PRE_PH_B + m * 272 + hs * 128);
                uint4* dstp = (uint4*)((__half*)g_P + (size_t)gn * 256 + nh * 128 + hs * 64);
                #pragma unroll
                for (int s = 0; s < 8; ++s) dstp[s] = srcp[s];
            }
        }
    }
}

// ---------------------------------------------------------------------------
// SMEM layout for k_edge (BYTE offsets):
//   H/EA @0     : h fp16 [128][136h] stride 272B (EA [128][40h] overlays during
//                 staging/GEMM1), 34816B
//   PS   @34816 : Psum fp16 [128][136h] stride 272B (P_src+P_dst+b1), 34816B
//   W1C  @69632 : fp16 [128][40h] stride 80B, persistent
//   W2   @79872 : fp16 [64][136h] stride 272B, persistent
//   b1 @97280, b2 @97792, src @98048, dst @98560 -> total 99072B
// ---------------------------------------------------------------------------
#define H_B     0u
#define EA_B    0u
#define PS_B    34816u
#define W1C_B   69632u
#define W2_B    79872u
#define B1_B    97280u
#define B2_B    97792u
#define SRC_B   98048u
#define DST_B   98560u
#define SMEM_EDGE_BYTES 99072u

// ---------------------------------------------------------------------------
// Kernel 2: persistent fp16 mma edge MLP, register-resident h + split-source
// GEMM2 A operands.  128 edges/tile, 8 warps/CTA.
// ---------------------------------------------------------------------------
__global__ __launch_bounds__(256, 2) void k_edge(
    const int*   __restrict__ eidx,
    const float* __restrict__ ea,
    const float* __restrict__ W1,
    const float* __restrict__ b1,
    const float* __restrict__ W2g,
    const float* __restrict__ b2,
    float*       __restrict__ out,
    int E, int n_tiles)
{
    extern __shared__ __align__(16) char smc[];
    const uint32_t sb = smem_u32(smc);
    const int t   = threadIdx.x;
    const int wid = t >> 5;
    const int lid = t & 31;
    const int qr  = lid >> 2;
    const int ql  = lid & 3;
    const int wm  = wid & 3;       // M quadrant (rows wm*32..+32)
    const int wn  = wid >> 2;      // 0/1: h K-half AND output N-half
    const int lm  = lid & 7;
    const int lq3 = lid >> 3;
    const int lq4 = lid >> 4;

    int*   s_src = (int*)(smc + SRC_B);
    int*   s_dst = (int*)(smc + DST_B);
    float* s_b1  = (float*)(smc + B1_B);
    float* s_b2  = (float*)(smc + B2_B);

    // ======== CTA prologue: persistent W1C, W2, biases ========
    {
        int n = t >> 1, hs = t & 1;
        const float4* src = (const float4*)(W1 + n * D_IN1 + 128 + hs * 16);
        float4 v0 = src[0], v1 = src[1], v2 = src[2], v3 = src[3];
        uint4 p0 = make_uint4(pack_h2(v0.x, v0.y), pack_h2(v0.z, v0.w),
                              pack_h2(v1.x, v1.y), pack_h2(v1.z, v1.w));
        uint4 p1 = make_uint4(pack_h2(v2.x, v2.y), pack_h2(v2.z, v2.w),
                              pack_h2(v3.x, v3.y), pack_h2(v3.z, v3.w));
        *(uint4*)(smc + W1C_B + n * 80 + hs * 32)      = p0;
        *(uint4*)(smc + W1C_B + n * 80 + hs * 32 + 16) = p1;
    }
    {
        int n = t >> 2, q = t & 3;
        const float4* src = (const float4*)(W2g + n * 128 + q * 32);
        #pragma unroll
        for (int s = 0; s < 2; ++s) {
            float4 v0 = src[4 * s + 0], v1 = src[4 * s + 1],
                   v2 = src[4 * s + 2], v3 = src[4 * s + 3];
            uint4 pa = make_uint4(pack_h2(v0.x, v0.y), pack_h2(v0.z, v0.w),
                                  pack_h2(v1.x, v1.y), pack_h2(v1.z, v1.w));
            uint4 pb = make_uint4(pack_h2(v2.x, v2.y), pack_h2(v2.z, v2.w),
                                  pack_h2(v3.x, v3.y), pack_h2(v3.z, v3.w));
            *(uint4*)(smc + W2_B + n * 272 + q * 64 + s * 32)      = pa;
            *(uint4*)(smc + W2_B + n * 272 + q * 64 + s * 32 + 16) = pb;
        }
    }
    if (t < 128)      s_b1[t] = b1[t];
    else if (t < 192) s_b2[t - 128] = b2[t - 128];
    __syncthreads();

    float2 bb2[4];
    #pragma unroll
    for (int j = 0; j < 4; ++j)
        bb2[j] = *(const float2*)(s_b2 + wn * 32 + j * 8 + 2 * ql);
    const float4 bb1 = *(const float4*)(s_b1 + 4 * lid);   // used in Psum gather

    // ---- ldmatrix per-lane base addresses ----
    uint32_t a1b[2], b1b[4], a2o[2], b2b[2];
    #pragma unroll
    for (int i = 0; i < 2; ++i)
        a1b[i] = sb + EA_B + (uint32_t)((wm * 32 + i * 16 + ((lq3 & 1) << 3) + lm) * 80)
               + (uint32_t)((lq3 >> 1) * 16);
    #pragma unroll
    for (int jj = 0; jj < 4; ++jj)
        b1b[jj] = sb + W1C_B + (uint32_t)((wn * 64 + jj * 16 + lq4 * 8 + lm) * 80)
                + (uint32_t)((lq3 & 1) * 16);
    // GEMM2 A (other K-half) from H
    #pragma unroll
    for (int i = 0; i < 2; ++i)
        a2o[i] = sb + H_B + (uint32_t)((wm * 32 + i * 16 + ((lq3 & 1) << 3) + lm) * 272)
               + (uint32_t)((lq3 >> 1) * 16) + (uint32_t)((wn ^ 1) * 128);
    #pragma unroll
    for (int jj = 0; jj < 2; ++jj)
        b2b[jj] = sb + W2_B + (uint32_t)((wn * 32 + jj * 16 + lq4 * 8 + lm) * 272)
                + (uint32_t)((lq3 & 1) * 16);

    const int m0 = wid * 16;                 // Psum gather rows for this warp

    // ======== persistent tile loop ========
    for (int tile = blockIdx.x; tile < n_tiles; tile += gridDim.x) {
        const int ebase = tile * E_TILE;

        // ---- stage ea -> fp16 [128][40h] (overlays H) + indices ----
        {
            int m = t >> 1, hs = t & 1;
            int ge = ebase + m;
            float4 v0, v1, v2, v3;
            if (ge < E) {
                const float4* src = (const float4*)(ea + (size_t)ge * DIM_EDGE + hs * 16);
                v0 = src[0]; v1 = src[1]; v2 = src[2]; v3 = src[3];
            } else {
                v0 = v1 = v2 = v3 = make_float4(0.f, 0.f, 0.f, 0.f);
            }
            uint4 p0 = make_uint4(pack_h2(v0.x, v0.y), pack_h2(v0.z, v0.w),
                                  pack_h2(v1.x, v1.y), pack_h2(v1.z, v1.w));
            uint4 p1 = make_uint4(pack_h2(v2.x, v2.y), pack_h2(v2.z, v2.w),
                                  pack_h2(v3.x, v3.y), pack_h2(v3.z, v3.w));
            *(uint4*)(smc + EA_B + m * 80 + hs * 32)      = p0;
            *(uint4*)(smc + EA_B + m * 80 + hs * 32 + 16) = p1;
        }
        if (t < 128) {
            int e = ebase + t;
            s_src[t] = (e < E) ? eidx[e] : 0;
        } else {
            int e = ebase + (t - 128);
            s_dst[t - 128] = (e < E) ? eidx[E + e] : 0;
        }
        __syncthreads();                       // (A)

        // ---- Psum = fp16(P_src + P_dst + b1) -> PS  (LDG latency overlaps
        //      with GEMM1 work of sibling warps) ----
        #pragma unroll
        for (int g = 0; g < 16; g += 8) {
            uint2 us[8], ud[8];
            #pragma unroll
            for (int r = 0; r < 8; ++r) {
                int m = m0 + g + r;
                us[r] = *(const uint2*)((const __half*)g_P + (size_t)s_src[m] * 256 + 4 * lid);
                ud[r] = *(const uint2*)((const __half*)g_P + (size_t)s_dst[m] * 256 + 128 + 4 * lid);
            }
            #pragma unroll
            for (int r = 0; r < 8; ++r) {
                float2 s01 = h2f2(us[r].x), s23 = h2f2(us[r].y);
                float2 d01 = h2f2(ud[r].x), d23 = h2f2(ud[r].y);
                float p0 = s01.x + d01.x + bb1.x;
                float p1 = s01.y + d01.y + bb1.y;
                float p2 = s23.x + d23.x + bb1.z;
                float p3 = s23.y + d23.y + bb1.w;
                *(uint2*)(smc + PS_B + (m0 + g + r) * 272 + 8 * lid) =
                    make_uint2(pack_h2(p0, p1), pack_h2(p2, p3));
            }
        }

        // ---- GEMM1: C1[128x128] = ea @ W1c^T (per warp M=32, N=64) ----
        float acc1[2][8][4];
        #pragma unroll
        for (int i = 0; i < 2; ++i)
            #pragma unroll
            for (int j = 0; j < 8; ++j)
                #pragma unroll
                for (int c = 0; c < 4; ++c) acc1[i][j][c] = 0.f;

        #pragma unroll
        for (int ks = 0; ks < 2; ++ks) {
            uint32_t A[2][4], B[4][4];
            ldsm_x4(A[0], a1b[0] + ks * 32);
            ldsm_x4(A[1], a1b[1] + ks * 32);
            #pragma unroll
            for (int jj = 0; jj < 4; ++jj)
                ldsm_x4(B[jj], b1b[jj] + ks * 32);
            #pragma unroll
            for (int i = 0; i < 2; ++i)
                #pragma unroll
                for (int j = 0; j < 8; ++j)
                    mma_f16(acc1[i][j], A[i], &B[j >> 1][(j & 1) * 2]);
        }
        __syncthreads();                       // (B) Psum STS done; EA reads done

        // ---- convert: h = leaky(C1 + Psum); pack into GEMM2 A-frags (own
        //      K-half) in registers AND STS fp16 h to H for partner warp ----
        uint32_t hA[2][4][4];
        #pragma unroll
        for (int i = 0; i < 2; ++i) {
            const int r0 = wm * 32 + i * 16 + qr;
            const int r1 = r0 + 8;
            #pragma unroll
            for (int ks = 0; ks < 4; ++ks) {
                #pragma unroll
                for (int jj = 0; jj < 2; ++jj) {
                    const int j = 2 * ks + jj;
                    const uint32_t off = (uint32_t)(wn * 128 + j * 16 + ql * 4);
                    float2 p0 = h2f2(*(const uint32_t*)(smc + PS_B + r0 * 272 + off));
                    float2 p1 = h2f2(*(const uint32_t*)(smc + PS_B + r1 * 272 + off));
                    float h0 = acc1[i][j][0] + p0.x;
                    float h1 = acc1[i][j][1] + p0.y;
                    float h2 = acc1[i][j][2] + p1.x;
                    float h3 = acc1[i][j][3] + p1.y;
                    h0 = (h0 >= 0.f) ? h0 : NEG_SLOPE * h0;
                    h1 = (h1 >= 0.f) ? h1 : NEG_SLOPE * h1;
                    h2 = (h2 >= 0.f) ? h2 : NEG_SLOPE * h2;
                    h3 = (h3 >= 0.f) ? h3 : NEG_SLOPE * h3;
                    uint32_t u0 = pack_h2(h0, h1);
                    uint32_t u1 = pack_h2(h2, h3);
                    hA[i][ks][jj * 2 + 0] = u0;
                    hA[i][ks][jj * 2 + 1] = u1;
                    *(uint32_t*)(smc + H_B + r0 * 272 + off) = u0;
                    *(uint32_t*)(smc + H_B + r1 * 272 + off) = u1;
                }
            }
        }
        __syncthreads();                       // (C) h visible for partner

        // ---- GEMM2: C2[128x64] = h @ W2^T; A own half from regs, other
        //      half via ldsm; per warp M=32, N=32 ----
        float acc2[2][4][4];
        #pragma unroll
        for (int i = 0; i < 2; ++i)
            #pragma unroll
            for (int j = 0; j < 4; ++j)
                #pragma unroll
                for (int c = 0; c < 4; ++c) acc2[i][j][c] = 0.f;

        #pragma unroll
        for (int ksl = 0; ksl < 4; ++ksl) {    // own K-half (global k = wn*64+16ksl)
            uint32_t B[2][4];
            ldsm_x4(B[0], b2b[0] + (uint32_t)(wn * 128) + ksl * 32);
            ldsm_x4(B[1], b2b[1] + (uint32_t)(wn * 128) + ksl * 32);
            #pragma unroll
            for (int i = 0; i < 2; ++i)
                #pragma unroll
                for (int j = 0; j < 4; ++j)
                    mma_f16(acc2[i][j], hA[i][ksl], &B[j >> 1][(j & 1) * 2]);
        }
        #pragma unroll
        for (int ksl = 0; ksl < 4; ++ksl) {    // other K-half via ldsm
            uint32_t A[2][4], B[2][4];
            ldsm_x4(A[0], a2o[0] + ksl * 32);
            ldsm_x4(A[1], a2o[1] + ksl * 32);
            ldsm_x4(B[0], b2b[0] + (uint32_t)((wn ^ 1) * 128) + ksl * 32);
            ldsm_x4(B[1], b2b[1] + (uint32_t)((wn ^ 1) * 128) + ksl * 32);
            #pragma unroll
            for (int i = 0; i < 2; ++i)
                #pragma unroll
                for (int j = 0; j < 4; ++j)
                    mma_f16(acc2[i][j], A[i], &B[j >> 1][(j & 1) * 2]);
        }

        // ---- Epilogue: direct STG (+b2) ----
        #pragma unroll
        for (int i = 0; i < 2; ++i) {
            int r = wm * 32 + i * 16 + qr;
            int ge0 = ebase + r;
            int ge1 = ge0 + 8;
            #pragma unroll
            for (int j = 0; j < 4; ++j) {
                int c = wn * 32 + j * 8 + 2 * ql;
                if (ge0 < E)
                    *(float2*)(out + (size_t)ge0 * OUT_DIM + c) =
                        make_float2(acc2[i][j][0] + bb2[j].x, acc2[i][j][1] + bb2[j].y);
                if (ge1 < E)
                    *(float2*)(out + (size_t)ge1 * OUT_DIM + c) =
                        make_float2(acc2[i][j][2] + bb2[j].x, acc2[i][j][3] + bb2[j].y);
            }
        }
        __syncthreads();                       // (D) H/PS free for next tile
    }
}

// ---------------------------------------------------------------------------
extern "C" void kernel_launch(void* const* d_in, const int* in_sizes, int n_in,
                              void* d_out, int out_size)
{
    const float* x    = (const float*)d_in[0];
    const int*   eidx = (const int*)  d_in[1];
    const float* ea   = (const float*)d_in[2];
    const float* W1   = (const float*)d_in[3];
    const float* b1   = (const float*)d_in[4];
    const float* W2   = (const float*)d_in[5];
    const float* b2   = (const float*)d_in[6];
    float* out = (float*)d_out;

    int n_nodes = in_sizes[0] / DIM_NODE;
    if (n_nodes > MAX_NODES) n_nodes = MAX_NODES;
    int E = in_sizes[2] / DIM_EDGE;
    int n_tiles = (E + E_TILE - 1) / E_TILE;

    cudaFuncSetAttribute(k_precompute, cudaFuncAttributeMaxDynamicSharedMemorySize, (int)PRE_SMEM);
    cudaFuncSetAttribute(k_edge, cudaFuncAttributeMaxDynamicSharedMemorySize, (int)SMEM_EDGE_BYTES);

    int n_blocks = 148 * 8;
    if (n_blocks > n_tiles) n_blocks = n_tiles;

    k_precompute<<<(n_nodes + 127) / 128, 256, PRE_SMEM>>>(x, W1, n_nodes);
    k_edge<<<n_blocks, 256, SMEM_EDGE_BYTES>>>(eidx, ea, W1, b1, W2, b2, out, E, n_tiles);
}

// round 12
// speedup vs baseline: 1.8382x; 1.0762x over previous
#include <cuda_runtime.h>
#include <cuda_fp16.h>
#include <cstdint>

#define DIM_NODE 64
#define DIM_EDGE 32
#define D_IN1    160
#define OUT_DIM  64
#define MAX_NODES 50000
#define E_TILE   128
#define NEG_SLOPE 0.01f

// Per-node precomputed partials (fp16): P[n][0:128] = x[n]@W1a^T, P[n][128:256] = x[n]@W1b^T
__device__ __half g_P[(size_t)MAX_NODES * 256];
__device__ unsigned g_barrier;   // epoch-accumulating grid barrier counter

__device__ __forceinline__ void mma_f16(float* d, const uint32_t* a, const uint32_t* b) {
    asm volatile(
        "mma.sync.aligned.m16n8k16.row.col.f32.f16.f16.f32 "
        "{%0,%1,%2,%3}, {%4,%5,%6,%7}, {%8,%9}, {%0,%1,%2,%3};"
        : "+f"(d[0]), "+f"(d[1]), "+f"(d[2]), "+f"(d[3])
        : "r"(a[0]), "r"(a[1]), "r"(a[2]), "r"(a[3]), "r"(b[0]), "r"(b[1]));
}
__device__ __forceinline__ void ldsm_x4(uint32_t* r, uint32_t addr) {
    asm volatile("ldmatrix.sync.aligned.m8n8.x4.shared.b16 {%0,%1,%2,%3}, [%4];"
        : "=r"(r[0]), "=r"(r[1]), "=r"(r[2]), "=r"(r[3]) : "r"(addr));
}
__device__ __forceinline__ uint32_t smem_u32(const void* p) {
    uint32_t a;
    asm("{ .reg .u64 t; cvta.to.shared.u64 t, %1; cvt.u32.u64 %0, t; }" : "=r"(a) : "l"(p));
    return a;
}
__device__ __forceinline__ uint32_t pack_h2(float a, float b) {
    __half2 h = __floats2half2_rn(a, b);
    return *(uint32_t*)&h;
}
__device__ __forceinline__ float2 h2f2(uint32_t u) {
    __half2 h = *(__half2*)&u;
    return __half22float2(h);
}

// ---------------------------------------------------------------------------
// SMEM layout (BYTE offsets).
// Phase 1 (node precompute) overlays the same 99KB:
//   XT @0 [128][144B], V @18432 [256][144B], PH @55296 [128][272B]  (<=90112)
// Phase 2 (edge loop):
//   H/EA @0, PS @34816, W1C @69632, W2 @79872, b1 @97280, b2 @97792
// ---------------------------------------------------------------------------
#define PRE_XT_B  0u
#define PRE_V_B   18432u
#define PRE_PH_B  55296u

#define H_B     0u
#define EA_B    0u
#define PS_B    34816u
#define W1C_B   69632u
#define W2_B    79872u
#define B1_B    97280u
#define B2_B    97792u
#define SMEM_BYTES 98304u

// ---------------------------------------------------------------------------
// Fused persistent kernel: phase 1 node precompute -> grid barrier -> phase 2
// edge MLP tiles.  256 threads, 2 CTAs/SM guaranteed resident.
// ---------------------------------------------------------------------------
__global__ __launch_bounds__(256, 2) void k_fused(
    const float* __restrict__ x,
    const int*   __restrict__ eidx,
    const float* __restrict__ ea,
    const float* __restrict__ W1,
    const float* __restrict__ b1,
    const float* __restrict__ W2g,
    const float* __restrict__ b2,
    float*       __restrict__ out,
    int n_nodes, int E, int n_tiles, int n_node_tiles)
{
    extern __shared__ __align__(16) char smc[];
    const uint32_t sb = smem_u32(smc);
    const int t   = threadIdx.x;
    const int wid = t >> 5;
    const int lid = t & 31;
    const int qr  = lid >> 2;
    const int ql  = lid & 3;
    const int wm  = wid & 3;       // M quadrant (rows wm*32..+32)
    const int wn  = wid >> 2;      // 0/1: h K-half AND output N-half
    const int lm  = lid & 7;
    const int lq3 = lid >> 3;
    const int lq4 = lid >> 4;

    // ======================= PHASE 1: node precompute =======================
    {
        // stage V (combined 256x64 weight) once: fp16 [256][144B]
        {
            int c = t;
            const float* src = (c < 128) ? (W1 + c * D_IN1) : (W1 + (c - 128) * D_IN1 + 64);
            #pragma unroll
            for (int s = 0; s < 4; ++s) {
                float4 v0 = *(const float4*)(src + s * 16 + 0);
                float4 v1 = *(const float4*)(src + s * 16 + 4);
                float4 v2 = *(const float4*)(src + s * 16 + 8);
                float4 v3 = *(const float4*)(src + s * 16 + 12);
                uint4 pa = make_uint4(pack_h2(v0.x, v0.y), pack_h2(v0.z, v0.w),
                                      pack_h2(v1.x, v1.y), pack_h2(v1.z, v1.w));
                uint4 pb = make_uint4(pack_h2(v2.x, v2.y), pack_h2(v2.z, v2.w),
                                      pack_h2(v3.x, v3.y), pack_h2(v3.z, v3.w));
                *(uint4*)(smc + PRE_V_B + c * 144 + s * 32)      = pa;
                *(uint4*)(smc + PRE_V_B + c * 144 + s * 32 + 16) = pb;
            }
        }
        uint32_t ab[2];
        #pragma unroll
        for (int i = 0; i < 2; ++i)
            ab[i] = sb + PRE_XT_B + (uint32_t)((wm * 32 + i * 16 + ((lq3 & 1) << 3) + lm) * 144)
                  + (uint32_t)((lq3 >> 1) * 16);

        for (int nt = blockIdx.x; nt < n_node_tiles; nt += gridDim.x) {
            const int node0 = nt * 128;
            // stage x tile fp16 [128][144B]
            {
                int m = t >> 1, hs = t & 1;
                int gn = node0 + m;
                #pragma unroll
                for (int s = 0; s < 2; ++s) {
                    float4 v0, v1, v2, v3;
                    if (gn < n_nodes) {
                        const float4* src = (const float4*)(x + (size_t)gn * DIM_NODE + hs * 32 + s * 16);
                        v0 = src[0]; v1 = src[1]; v2 = src[2]; v3 = src[3];
                    } else {
                        v0 = v1 = v2 = v3 = make_float4(0.f, 0.f, 0.f, 0.f);
                    }
                    uint4 pa = make_uint4(pack_h2(v0.x, v0.y), pack_h2(v0.z, v0.w),
                                          pack_h2(v1.x, v1.y), pack_h2(v1.z, v1.w));
                    uint4 pb = make_uint4(pack_h2(v2.x, v2.y), pack_h2(v2.z, v2.w),
                                          pack_h2(v3.x, v3.y), pack_h2(v3.z, v3.w));
                    *(uint4*)(smc + PRE_XT_B + m * 144 + hs * 64 + s * 32)      = pa;
                    *(uint4*)(smc + PRE_XT_B + m * 144 + hs * 64 + s * 32 + 16) = pb;
                }
            }
            __syncthreads();

            #pragma unroll
            for (int nh = 0; nh < 2; ++nh) {
                if (nh) __syncthreads();
                float acc[2][8][4];
                #pragma unroll
                for (int i = 0; i < 2; ++i)
                    #pragma unroll
                    for (int j = 0; j < 8; ++j)
                        #pragma unroll
                        for (int c = 0; c < 4; ++c) acc[i][j][c] = 0.f;
                #pragma unroll
                for (int ks = 0; ks < 4; ++ks) {
                    uint32_t A[2][4], B[4][4];
                    ldsm_x4(A[0], ab[0] + ks * 32);
                    ldsm_x4(A[1], ab[1] + ks * 32);
                    #pragma unroll
                    for (int jj = 0; jj < 4; ++jj) {
                        int n = nh * 128 + wn * 64 + jj * 16 + lq4 * 8 + lm;
                        ldsm_x4(B[jj], sb + PRE_V_B + (uint32_t)(n * 144)
                                       + (uint32_t)((lq3 & 1) * 16) + ks * 32);
                    }
                    #pragma unroll
                    for (int i = 0; i < 2; ++i)
                        #pragma unroll
                        for (int j = 0; j < 8; ++j)
                            mma_f16(acc[i][j], A[i], &B[j >> 1][(j & 1) * 2]);
                }
                #pragma unroll
                for (int i = 0; i < 2; ++i) {
                    int r = wm * 32 + i * 16 + qr;
                    #pragma unroll
                    for (int j = 0; j < 8; ++j) {
                        int c = wn * 64 + j * 8 + 2 * ql;
                        *(uint32_t*)(smc + PRE_PH_B + r * 272 + 2 * c) =
                            pack_h2(acc[i][j][0], acc[i][j][1]);
                        *(uint32_t*)(smc + PRE_PH_B + (r + 8) * 272 + 2 * c) =
                            pack_h2(acc[i][j][2], acc[i][j][3]);
                    }
                }
                __syncthreads();
                {
                    int m = t >> 1, hs = t & 1;
                    int gn = node0 + m;
                    if (gn < n_nodes) {
                        const uint4* srcp = (const uint4*)(smc + PRE_PH_B + m * 272 + hs * 128);
                        uint4* dstp = (uint4*)((__half*)g_P + (size_t)gn * 256 + nh * 128 + hs * 64);
                        #pragma unroll
                        for (int s = 0; s < 8; ++s) dstp[s] = srcp[s];
                    }
                }
            }
            __syncthreads();
        }
    }

    // ======================= GRID BARRIER (epoch-based) ======================
    __threadfence();
    __syncthreads();
    if (t == 0) {
        unsigned v = *((volatile unsigned*)&g_barrier);
        unsigned target = (v / gridDim.x + 1u) * gridDim.x;
        atomicAdd(&g_barrier, 1u);
        while (*((volatile unsigned*)&g_barrier) < target) { }
    }
    __syncthreads();

    // ======================= PHASE 2 prologue: weights =======================
    {
        int n = t >> 1, hs = t & 1;
        const float4* src = (const float4*)(W1 + n * D_IN1 + 128 + hs * 16);
        float4 v0 = src[0], v1 = src[1], v2 = src[2], v3 = src[3];
        uint4 p0 = make_uint4(pack_h2(v0.x, v0.y), pack_h2(v0.z, v0.w),
                              pack_h2(v1.x, v1.y), pack_h2(v1.z, v1.w));
        uint4 p1 = make_uint4(pack_h2(v2.x, v2.y), pack_h2(v2.z, v2.w),
                              pack_h2(v3.x, v3.y), pack_h2(v3.z, v3.w));
        *(uint4*)(smc + W1C_B + n * 80 + hs * 32)      = p0;
        *(uint4*)(smc + W1C_B + n * 80 + hs * 32 + 16) = p1;
    }
    {
        int n = t >> 2, q = t & 3;
        const float4* src = (const float4*)(W2g + n * 128 + q * 32);
        #pragma unroll
        for (int s = 0; s < 2; ++s) {
            float4 v0 = src[4 * s + 0], v1 = src[4 * s + 1],
                   v2 = src[4 * s + 2], v3 = src[4 * s + 3];
            uint4 pa = make_uint4(pack_h2(v0.x, v0.y), pack_h2(v0.z, v0.w),
                                  pack_h2(v1.x, v1.y), pack_h2(v1.z, v1.w));
            uint4 pb = make_uint4(pack_h2(v2.x, v2.y), pack_h2(v2.z, v2.w),
                                  pack_h2(v3.x, v3.y), pack_h2(v3.z, v3.w));
            *(uint4*)(smc + W2_B + n * 272 + q * 64 + s * 32)      = pa;
            *(uint4*)(smc + W2_B + n * 272 + q * 64 + s * 32 + 16) = pb;
        }
    }
    if (t < 128)      ((float*)(smc + B1_B))[t] = b1[t];
    else if (t < 192) ((float*)(smc + B2_B))[t - 128] = b2[t - 128];
    __syncthreads();

    float2 bb2[4];
    #pragma unroll
    for (int j = 0; j < 4; ++j)
        bb2[j] = *(const float2*)((float*)(smc + B2_B) + wn * 32 + j * 8 + 2 * ql);
    const float4 bb1 = *(const float4*)((float*)(smc + B1_B) + 4 * lid);

    // ---- ldmatrix per-lane base addresses ----
    uint32_t a1b[2], b1b[4], a2o[2], b2b[2];
    #pragma unroll
    for (int i = 0; i < 2; ++i)
        a1b[i] = sb + EA_B + (uint32_t)((wm * 32 + i * 16 + ((lq3 & 1) << 3) + lm) * 80)
               + (uint32_t)((lq3 >> 1) * 16);
    #pragma unroll
    for (int jj = 0; jj < 4; ++jj)
        b1b[jj] = sb + W1C_B + (uint32_t)((wn * 64 + jj * 16 + lq4 * 8 + lm) * 80)
                + (uint32_t)((lq3 & 1) * 16);
    #pragma unroll
    for (int i = 0; i < 2; ++i)
        a2o[i] = sb + H_B + (uint32_t)((wm * 32 + i * 16 + ((lq3 & 1) << 3) + lm) * 272)
               + (uint32_t)((lq3 >> 1) * 16) + (uint32_t)((wn ^ 1) * 128);
    #pragma unroll
    for (int jj = 0; jj < 2; ++jj)
        b2b[jj] = sb + W2_B + (uint32_t)((wn * 32 + jj * 16 + lq4 * 8 + lm) * 272)
                + (uint32_t)((lq3 & 1) * 16);

    const int m0 = wid * 16;

    // ======================= PHASE 2: edge tile loop =========================
    for (int tile = blockIdx.x; tile < n_tiles; tile += gridDim.x) {
        const int ebase = tile * E_TILE;

        // ---- per-warp edge indices: lanes 0-15 src rows, 16-31 dst rows ----
        int my_idx = 0;
        {
            int eM = ebase + m0 + (lid & 15);
            if (eM < E) my_idx = (lid < 16) ? eidx[eM] : eidx[E + eM];
        }

        // ---- issue all Psum gather LDGs up front (latency overlaps staging) --
        uint2 us0[8], ud0[8], us1[8], ud1[8];
        #pragma unroll
        for (int r = 0; r < 8; ++r) {
            int si = __shfl_sync(0xffffffffu, my_idx, r);
            int di = __shfl_sync(0xffffffffu, my_idx, 16 + r);
            us0[r] = *(const uint2*)((const __half*)g_P + (size_t)si * 256 + 4 * lid);
            ud0[r] = *(const uint2*)((const __half*)g_P + (size_t)di * 256 + 128 + 4 * lid);
        }
        #pragma unroll
        for (int r = 0; r < 8; ++r) {
            int si = __shfl_sync(0xffffffffu, my_idx, 8 + r);
            int di = __shfl_sync(0xffffffffu, my_idx, 24 + r);
            us1[r] = *(const uint2*)((const __half*)g_P + (size_t)si * 256 + 4 * lid);
            ud1[r] = *(const uint2*)((const __half*)g_P + (size_t)di * 256 + 128 + 4 * lid);
        }

        // ---- stage ea -> fp16 [128][40h] (overlays H) ----
        {
            int m = t >> 1, hs = t & 1;
            int ge = ebase + m;
            float4 v0, v1, v2, v3;
            if (ge < E) {
                const float4* src = (const float4*)(ea + (size_t)ge * DIM_EDGE + hs * 16);
                v0 = src[0]; v1 = src[1]; v2 = src[2]; v3 = src[3];
            } else {
                v0 = v1 = v2 = v3 = make_float4(0.f, 0.f, 0.f, 0.f);
            }
            uint4 p0 = make_uint4(pack_h2(v0.x, v0.y), pack_h2(v0.z, v0.w),
                                  pack_h2(v1.x, v1.y), pack_h2(v1.z, v1.w));
            uint4 p1 = make_uint4(pack_h2(v2.x, v2.y), pack_h2(v2.z, v2.w),
                                  pack_h2(v3.x, v3.y), pack_h2(v3.z, v3.w));
            *(uint4*)(smc + EA_B + m * 80 + hs * 32)      = p0;
            *(uint4*)(smc + EA_B + m * 80 + hs * 32 + 16) = p1;
        }

        // ---- Psum = fp16(P_src + P_dst + b1) -> PS ----
        #pragma unroll
        for (int r = 0; r < 8; ++r) {
            float2 s01 = h2f2(us0[r].x), s23 = h2f2(us0[r].y);
            float2 d01 = h2f2(ud0[r].x), d23 = h2f2(ud0[r].y);
            float p0 = s01.x + d01.x + bb1.x;
            float p1 = s01.y + d01.y + bb1.y;
            float p2 = s23.x + d23.x + bb1.z;
            float p3 = s23.y + d23.y + bb1.w;
            *(uint2*)(smc + PS_B + (m0 + r) * 272 + 8 * lid) =
                make_uint2(pack_h2(p0, p1), pack_h2(p2, p3));
        }
        #pragma unroll
        for (int r = 0; r < 8; ++r) {
            float2 s01 = h2f2(us1[r].x), s23 = h2f2(us1[r].y);
            float2 d01 = h2f2(ud1[r].x), d23 = h2f2(ud1[r].y);
            float p0 = s01.x + d01.x + bb1.x;
            float p1 = s01.y + d01.y + bb1.y;
            float p2 = s23.x + d23.x + bb1.z;
            float p3 = s23.y + d23.y + bb1.w;
            *(uint2*)(smc + PS_B + (m0 + 8 + r) * 272 + 8 * lid) =
                make_uint2(pack_h2(p0, p1), pack_h2(p2, p3));
        }
        __syncthreads();                       // (A) ea + PS staged

        // ---- GEMM1: C1[128x128] = ea @ W1c^T (per warp M=32, N=64) ----
        float acc1[2][8][4];
        #pragma unroll
        for (int i = 0; i < 2; ++i)
            #pragma unroll
            for (int j = 0; j < 8; ++j)
                #pragma unroll
                for (int c = 0; c < 4; ++c) acc1[i][j][c] = 0.f;

        #pragma unroll
        for (int ks = 0; ks < 2; ++ks) {
            uint32_t A[2][4], B[4][4];
            ldsm_x4(A[0], a1b[0] + ks * 32);
            ldsm_x4(A[1], a1b[1] + ks * 32);
            #pragma unroll
            for (int jj = 0; jj < 4; ++jj)
                ldsm_x4(B[jj], b1b[jj] + ks * 32);
            #pragma unroll
            for (int i = 0; i < 2; ++i)
                #pragma unroll
                for (int j = 0; j < 8; ++j)
                    mma_f16(acc1[i][j], A[i], &B[j >> 1][(j & 1) * 2]);
        }
        __syncthreads();                       // (B) EA reads done

        // ---- convert: h = leaky(C1 + Psum) -> GEMM2 A-frags + H STS ----
        uint32_t hA[2][4][4];
        #pragma unroll
        for (int i = 0; i < 2; ++i) {
            const int r0 = wm * 32 + i * 16 + qr;
            const int r1 = r0 + 8;
            #pragma unroll
            for (int ks = 0; ks < 4; ++ks) {
                #pragma unroll
                for (int jj = 0; jj < 2; ++jj) {
                    const int j = 2 * ks + jj;
                    const uint32_t off = (uint32_t)(wn * 128 + j * 16 + ql * 4);
                    float2 p0 = h2f2(*(const uint32_t*)(smc + PS_B + r0 * 272 + off));
                    float2 p1 = h2f2(*(const uint32_t*)(smc + PS_B + r1 * 272 + off));
                    float h0 = acc1[i][j][0] + p0.x;
                    float h1 = acc1[i][j][1] + p0.y;
                    float h2 = acc1[i][j][2] + p1.x;
                    float h3 = acc1[i][j][3] + p1.y;
                    h0 = (h0 >= 0.f) ? h0 : NEG_SLOPE * h0;
                    h1 = (h1 >= 0.f) ? h1 : NEG_SLOPE * h1;
                    h2 = (h2 >= 0.f) ? h2 : NEG_SLOPE * h2;
                    h3 = (h3 >= 0.f) ? h3 : NEG_SLOPE * h3;
                    uint32_t u0 = pack_h2(h0, h1);
                    uint32_t u1 = pack_h2(h2, h3);
                    hA[i][ks][jj * 2 + 0] = u0;
                    hA[i][ks][jj * 2 + 1] = u1;
                    *(uint32_t*)(smc + H_B + r0 * 272 + off) = u0;
                    *(uint32_t*)(smc + H_B + r1 * 272 + off) = u1;
                }
            }
        }
        __syncthreads();                       // (C) h visible for partner

        // ---- GEMM2: own K-half from regs, other via ldsm; M=32, N=32 ----
        float acc2[2][4][4];
        #pragma unroll
        for (int i = 0; i < 2; ++i)
            #pragma unroll
            for (int j = 0; j < 4; ++j)
                #pragma unroll
                for (int c = 0; c < 4; ++c) acc2[i][j][c] = 0.f;

        #pragma unroll
        for (int ksl = 0; ksl < 4; ++ksl) {
            uint32_t B[2][4];
            ldsm_x4(B[0], b2b[0] + (uint32_t)(wn * 128) + ksl * 32);
            ldsm_x4(B[1], b2b[1] + (uint32_t)(wn * 128) + ksl * 32);
            #pragma unroll
            for (int i = 0; i < 2; ++i)
                #pragma unroll
                for (int j = 0; j < 4; ++j)
                    mma_f16(acc2[i][j], hA[i][ksl], &B[j >> 1][(j & 1) * 2]);
        }
        #pragma unroll
        for (int ksl = 0; ksl < 4; ++ksl) {
            uint32_t A[2][4], B[2][4];
            ldsm_x4(A[0], a2o[0] + ksl * 32);
            ldsm_x4(A[1], a2o[1] + ksl * 32);
            ldsm_x4(B[0], b2b[0] + (uint32_t)((wn ^ 1) * 128) + ksl * 32);
            ldsm_x4(B[1], b2b[1] + (uint32_t)((wn ^ 1) * 128) + ksl * 32);
            #pragma unroll
            for (int i = 0; i < 2; ++i)
                #pragma unroll
                for (int j = 0; j < 4; ++j)
                    mma_f16(acc2[i][j], A[i], &B[j >> 1][(j & 1) * 2]);
        }

        // ---- Epilogue: direct STG (+b2) ----
        #pragma unroll
        for (int i = 0; i < 2; ++i) {
            int r = wm * 32 + i * 16 + qr;
            int ge0 = ebase + r;
            int ge1 = ge0 + 8;
            #pragma unroll
            for (int j = 0; j < 4; ++j) {
                int c = wn * 32 + j * 8 + 2 * ql;
                if (ge0 < E)
                    *(float2*)(out + (size_t)ge0 * OUT_DIM + c) =
                        make_float2(acc2[i][j][0] + bb2[j].x, acc2[i][j][1] + bb2[j].y);
                if (ge1 < E)
                    *(float2*)(out + (size_t)ge1 * OUT_DIM + c) =
                        make_float2(acc2[i][j][2] + bb2[j].x, acc2[i][j][3] + bb2[j].y);
            }
        }
        __syncthreads();                       // (D) H/PS free for next tile
    }
}

// ---------------------------------------------------------------------------
extern "C" void kernel_launch(void* const* d_in, const int* in_sizes, int n_in,
                              void* d_out, int out_size)
{
    const float* x    = (const float*)d_in[0];
    const int*   eidx = (const int*)  d_in[1];
    const float* ea   = (const float*)d_in[2];
    const float* W1   = (const float*)d_in[3];
    const float* b1   = (const float*)d_in[4];
    const float* W2   = (const float*)d_in[5];
    const float* b2   = (const float*)d_in[6];
    float* out = (float*)d_out;

    int n_nodes = in_sizes[0] / DIM_NODE;
    if (n_nodes > MAX_NODES) n_nodes = MAX_NODES;
    int E = in_sizes[2] / DIM_EDGE;
    int n_tiles = (E + E_TILE - 1) / E_TILE;
    int n_node_tiles = (n_nodes + 127) / 128;

    static int n_sms = 0;
    if (n_sms == 0) {
        int dev = 0;
        cudaGetDevice(&dev);
        cudaDeviceGetAttribute(&n_sms, cudaDevAttrMultiProcessorCount, dev);
        if (n_sms <= 0) n_sms = 148;
    }
    int n_blocks = n_sms * 2;   // all resident (launch_bounds(256,2)) -> grid barrier safe

    cudaFuncSetAttribute(k_fused, cudaFuncAttributeMaxDynamicSharedMemorySize, (int)SMEM_BYTES);
    k_fused<<<n_blocks, 256, SMEM_BYTES>>>(x, eidx, ea, W1, b1, W2, b2, out,
                                           n_nodes, E, n_tiles, n_node_tiles);
}